// round 3
// baseline (speedup 1.0000x reference)
#include <cuda_runtime.h>
#include <cuda_fp16.h>
#include <cstdint>

#define Bb   64
#define Tt   256
#define Ii   256
#define Hh   1024
#define Gg   4096
#define Oo   256
#define K1   1280          // I + H
#define K2   2304          // I + H + H
#define NBLK 136
#define NTHR 256
#define HB   (Hh * Bb)     // 65536

// ---------------- device-global scratch (no cudaMalloc allowed) ----------------
__device__ __align__(16) __half g_W1[(size_t)Gg * K1];   // permuted rows, cols [x | h1]
__device__ __align__(16) __half g_W2[(size_t)Gg * K2];   // permuted rows, cols [x | h1 | h2]
__device__ __align__(16) __half g_Wl[(size_t)Oo * K1];   // cols [x | h2]
__device__ __align__(16) __half g_xh[(size_t)Tt * Ii * Bb]; // [t][i][b]
__device__ __align__(16) __half g_h1[2 * HB];            // [parity][u][b]
__device__ __align__(16) __half g_h2[2 * HB];
__device__ float g_c1[HB];
__device__ float g_c2[HB];
__device__ float g_b1[Gg];
__device__ float g_b2[Gg];
__device__ float g_bl[Oo];
__device__ unsigned g_bar;

// ---------------- prep kernels ----------------
__global__ void prep_w1(const float* __restrict__ Wih, const float* __restrict__ Whh,
                        const float* __restrict__ bi, const float* __restrict__ bh) {
    size_t idx = (size_t)blockIdx.x * blockDim.x + threadIdx.x;
    if (idx < (size_t)Gg * K1) {
        int r = (int)(idx / K1), k = (int)(idx - (size_t)r * K1);
        int u = r >> 2, gt = r & 3;
        int orow = gt * Hh + u;
        float v = (k < Ii) ? Wih[(size_t)orow * Ii + k] : Whh[(size_t)orow * Hh + (k - Ii)];
        g_W1[idx] = __float2half(v);
    }
    if (idx < Gg) {
        int u = (int)idx >> 2, gt = (int)idx & 3;
        g_b1[idx] = bi[gt * Hh + u] + bh[gt * Hh + u];
    }
}

__global__ void prep_w2(const float* __restrict__ Wih, const float* __restrict__ Whh,
                        const float* __restrict__ bi, const float* __restrict__ bh) {
    size_t idx = (size_t)blockIdx.x * blockDim.x + threadIdx.x;
    if (idx < (size_t)Gg * K2) {
        int r = (int)(idx / K2), k = (int)(idx - (size_t)r * K2);
        int u = r >> 2, gt = r & 3;
        int orow = gt * Hh + u;
        float v = (k < K1) ? Wih[(size_t)orow * K1 + k] : Whh[(size_t)orow * Hh + (k - K1)];
        g_W2[idx] = __float2half(v);
    }
    if (idx < Gg) {
        int u = (int)idx >> 2, gt = (int)idx & 3;
        g_b2[idx] = bi[gt * Hh + u] + bh[gt * Hh + u];
    }
}

__global__ void prep_wl(const float* __restrict__ Wl, const float* __restrict__ bl) {
    int idx = blockIdx.x * blockDim.x + threadIdx.x;
    if (idx < Oo * K1) g_Wl[idx] = __float2half(Wl[idx]);
    if (idx < Oo) g_bl[idx] = bl[idx];
}

__global__ void prep_x(const float* __restrict__ x) {
    size_t idx = (size_t)blockIdx.x * blockDim.x + threadIdx.x;
    if (idx < (size_t)Bb * Tt * Ii) {
        int b = (int)(idx / (Tt * Ii));
        int rem = (int)(idx - (size_t)b * Tt * Ii);
        int t = rem / Ii, i = rem - t * Ii;
        g_xh[(size_t)t * (Ii * Bb) + (size_t)i * Bb + b] = __float2half(x[idx]);
    }
}

__global__ void prep_init() {
    int idx = blockIdx.x * blockDim.x + threadIdx.x;
    if (idx < 2 * HB) { g_h1[idx] = __float2half(0.f); g_h2[idx] = __float2half(0.f); }
    if (idx < HB) { g_c1[idx] = 0.f; g_c2[idx] = 0.f; }
    if (idx == 0) g_bar = 0u;
}

// ---------------- persistent kernel helpers ----------------
struct Seg { const __half* z; int rows; };

__device__ __forceinline__ float sigf(float x) { return 1.f / (1.f + __expf(-x)); }

// grid barrier: arrive (atomic) + volatile poll; gpu-scope fences emit
// CCTL.IVALL on sm_103a -> flushes stale L1 lines of the h buffers.
__device__ __forceinline__ void gbar(unsigned target) {
    __threadfence();          // release this thread's stores (and IVALL)
    __syncthreads();
    if (threadIdx.x == 0) {
        atomicAdd(&g_bar, 1u);
        volatile unsigned* p = &g_bar;
        while (*p < target) { }
        __threadfence();      // acquire: invalidate L1 before readers proceed
    }
    __syncthreads();
}

// 32x64 tile GEMM: 8 warps, warp tile 16x16 (wm 0..1, wn 0..3), acc[2][4]
__device__ __forceinline__ void gemm_tile(
    const __half* __restrict__ W, int ldw,
    const Seg* segs, int nseg, float acc[2][4], int tid,
    __half (*sA)[72], __half (*sB)[72])
{
    const int wid = tid >> 5, lane = tid & 31;
    const int grp = lane >> 2, tig = lane & 3;
    const int wm = wid & 1, wn = wid >> 1;
    const int arow = wm * 16 + grp;
    int kofs = 0;
    for (int s = 0; s < nseg; ++s) {
        const __half* z = segs[s].z;
        const int rows = segs[s].rows;
        for (int kc = 0; kc < rows; kc += 64) {
            __syncthreads();
            {   // A: 32 rows x 64 cols
                int row = tid >> 3, c8 = (tid & 7) * 8;
                *(uint4*)&sA[row][c8] =
                    *(const uint4*)(W + (size_t)row * ldw + (kofs + kc) + c8);
            }
#pragma unroll
            for (int r = 0; r < 2; ++r) {   // B: 64 k-rows x 64 b-cols
                int idx = tid + r * 256;
                int krow = idx >> 3, b8 = (idx & 7) * 8;
                *(uint4*)&sB[krow][b8] = *(const uint4*)(z + (size_t)(kc + krow) * Bb + b8);
            }
            __syncthreads();
#pragma unroll
            for (int k16 = 0; k16 < 4; ++k16) {
                const int kb = k16 * 16;
                unsigned a0 = *(const unsigned*)&sA[arow    ][kb + tig * 2];
                unsigned a1 = *(const unsigned*)&sA[arow + 8][kb + tig * 2];
                unsigned a2 = *(const unsigned*)&sA[arow    ][kb + tig * 2 + 8];
                unsigned a3 = *(const unsigned*)&sA[arow + 8][kb + tig * 2 + 8];
#pragma unroll
                for (int nt = 0; nt < 2; ++nt) {
                    const int n = wn * 16 + nt * 8 + grp;
                    unsigned short x0 = *(const unsigned short*)&sB[kb + tig * 2    ][n];
                    unsigned short x1 = *(const unsigned short*)&sB[kb + tig * 2 + 1][n];
                    unsigned short x2 = *(const unsigned short*)&sB[kb + tig * 2 + 8][n];
                    unsigned short x3 = *(const unsigned short*)&sB[kb + tig * 2 + 9][n];
                    unsigned b0 = (unsigned)x0 | ((unsigned)x1 << 16);
                    unsigned b1 = (unsigned)x2 | ((unsigned)x3 << 16);
                    asm volatile(
                        "mma.sync.aligned.m16n8k16.row.col.f32.f16.f16.f32 "
                        "{%0,%1,%2,%3}, {%4,%5,%6,%7}, {%8,%9}, {%0,%1,%2,%3};\n"
                        : "+f"(acc[nt][0]), "+f"(acc[nt][1]),
                          "+f"(acc[nt][2]), "+f"(acc[nt][3])
                        : "r"(a0), "r"(a1), "r"(a2), "r"(a3), "r"(b0), "r"(b1));
                }
            }
        }
        kofs += rows;
    }
}

// LSTM pointwise: tile rows are 4u+gate -> 8 full units, CTA-local
__device__ __forceinline__ void epi_gates(
    float acc[2][4], int tid, int m0, const float* __restrict__ bias,
    float* __restrict__ cbuf, __half* __restrict__ hdst, float (*s_g)[66])
{
    const int wid = tid >> 5, lane = tid & 31;
    const int grp = lane >> 2, tig = lane & 3;
    const int wm = wid & 1, wn = wid >> 1;
    const int m = wm * 16 + grp;
#pragma unroll
    for (int nt = 0; nt < 2; ++nt) {
        const int n = wn * 16 + nt * 8 + tig * 2;
        s_g[m][n] = acc[nt][0];  s_g[m][n + 1] = acc[nt][1];
        s_g[m + 8][n] = acc[nt][2];  s_g[m + 8][n + 1] = acc[nt][3];
    }
    __syncthreads();
    const int u0 = m0 >> 2;
#pragma unroll
    for (int j = 0; j < 2; ++j) {
        const int pi = tid + j * 256;
        const int du = pi >> 6, b = pi & 63;
        float ig = s_g[4 * du + 0][b] + bias[m0 + 4 * du + 0];
        float fg = s_g[4 * du + 1][b] + bias[m0 + 4 * du + 1];
        float gg = s_g[4 * du + 2][b] + bias[m0 + 4 * du + 2];
        float og = s_g[4 * du + 3][b] + bias[m0 + 4 * du + 3];
        const int ci = (u0 + du) * Bb + b;
        float c = cbuf[ci];
        float cn = sigf(fg) * c + sigf(ig) * tanhf(gg);
        cbuf[ci] = cn;
        hdst[ci] = __float2half(sigf(og) * tanhf(cn));
    }
}

__device__ __forceinline__ void do_y(
    int tile, int t_y, int p, float* __restrict__ out, int tid,
    __half (*sA)[72], __half (*sB)[72])
{
    const int m0 = (tile - 128) * 32;
    float acc[2][4] = {{0.f,0.f,0.f,0.f},{0.f,0.f,0.f,0.f}};
    Seg segs[2] = { { g_xh + (size_t)t_y * (Ii * Bb), Ii },
                    { g_h2 + p * HB, Hh } };
    gemm_tile(g_Wl + (size_t)m0 * K1, K1, segs, 2, acc, tid, sA, sB);
    const int wid = tid >> 5, lane = tid & 31;
    const int grp = lane >> 2, tig = lane & 3;
    const int wm = wid & 1, wn = wid >> 1;
    const int m = m0 + wm * 16 + grp;
#pragma unroll
    for (int nt = 0; nt < 2; ++nt) {
        const int n = wn * 16 + nt * 8 + tig * 2;   // batch
        const size_t r0 = (size_t)n * (Tt * Oo) + (size_t)t_y * Oo;
        const size_t r1 = (size_t)(n + 1) * (Tt * Oo) + (size_t)t_y * Oo;
        out[r0 + m]     = acc[nt][0] + g_bl[m];
        out[r1 + m]     = acc[nt][1] + g_bl[m];
        out[r0 + m + 8] = acc[nt][2] + g_bl[m + 8];
        out[r1 + m + 8] = acc[nt][3] + g_bl[m + 8];
    }
}

// ---------------- persistent LSTM kernel ----------------
__global__ void __launch_bounds__(NTHR, 1) lstm_main(float* __restrict__ out) {
    __shared__ __align__(16) __half sA[32][72];
    __shared__ __align__(16) __half sB[64][72];
    __shared__ float s_g[32][66];
    const int tile = blockIdx.x;
    const int tid = threadIdx.x;
    unsigned ph = 0;

    for (int t = 0; t <= Tt; ++t) {
        const int p = t & 1;
        // -------- Phase A: gates1(t) on tiles 0..127, y(t-1) on tiles 128..135
        if (t < Tt) {
            if (tile < 128) {
                const int m0 = tile * 32;
                float acc[2][4] = {{0.f,0.f,0.f,0.f},{0.f,0.f,0.f,0.f}};
                Seg segs[2] = { { g_xh + (size_t)t * (Ii * Bb), Ii },
                                { g_h1 + (1 - p) * HB, Hh } };
                gemm_tile(g_W1 + (size_t)m0 * K1, K1, segs, 2, acc, tid, sA, sB);
                epi_gates(acc, tid, m0, g_b1, g_c1, g_h1 + p * HB, s_g);
            } else if (t > 0) {
                do_y(tile, t - 1, p, out, tid, sA, sB);
            }
        } else {
            if (tile >= 128) do_y(tile, t - 1, p, out, tid, sA, sB);
            break;
        }
        ph++; gbar(ph * NBLK);
        // -------- Phase B: gates2(t) on tiles 0..127
        if (tile < 128) {
            const int m0 = tile * 32;
            float acc[2][4] = {{0.f,0.f,0.f,0.f},{0.f,0.f,0.f,0.f}};
            Seg segs[3] = { { g_xh + (size_t)t * (Ii * Bb), Ii },
                            { g_h1 + p * HB, Hh },
                            { g_h2 + p * HB, Hh } };
            gemm_tile(g_W2 + (size_t)m0 * K2, K2, segs, 3, acc, tid, sA, sB);
            epi_gates(acc, tid, m0, g_b2, g_c2, g_h2 + (1 - p) * HB, s_g);
        }
        ph++; gbar(ph * NBLK);
    }
}

// ---------------- launch ----------------
extern "C" void kernel_launch(void* const* d_in, const int* in_sizes, int n_in,
                              void* d_out, int out_size) {
    const float* x    = (const float*)d_in[0];
    const float* Wih1 = (const float*)d_in[1];
    const float* Whh1 = (const float*)d_in[2];
    const float* bih1 = (const float*)d_in[3];
    const float* bhh1 = (const float*)d_in[4];
    const float* Wih2 = (const float*)d_in[5];
    const float* Whh2 = (const float*)d_in[6];
    const float* bih2 = (const float*)d_in[7];
    const float* bhh2 = (const float*)d_in[8];
    const float* Wl   = (const float*)d_in[9];
    const float* bl   = (const float*)d_in[10];
    float* out = (float*)d_out;

    prep_w1<<<((size_t)Gg * K1 + 255) / 256, 256>>>(Wih1, Whh1, bih1, bhh1);
    prep_w2<<<((size_t)Gg * K2 + 255) / 256, 256>>>(Wih2, Whh2, bih2, bhh2);
    prep_wl<<<(Oo * K1 + 255) / 256, 256>>>(Wl, bl);
    prep_x<<<((size_t)Bb * Tt * Ii + 255) / 256, 256>>>(x);
    prep_init<<<(2 * HB + 255) / 256, 256>>>();
    lstm_main<<<NBLK, NTHR>>>(out);
}

// round 5
// speedup vs baseline: 1.5534x; 1.5534x over previous
#include <cuda_runtime.h>
#include <cuda_fp16.h>
#include <cstdint>

#define Bb   64
#define Tt   256
#define Ii   256
#define Hh   1024
#define Gg   4096
#define Oo   256
#define K1   1280          // I + H
#define K2   2304          // I + H + H
#define NBLK 136
#define NTHR 256
#define HB   (Hh * Bb)     // 65536
#define PAD  72            // smem row padding (halves); stride 144B -> conflict-free ldmatrix

// ---------------- device-global scratch ----------------
__device__ __align__(16) __half g_W1[(size_t)Gg * K1];
__device__ __align__(16) __half g_W2[(size_t)Gg * K2];
__device__ __align__(16) __half g_Wl[(size_t)Oo * K1];
__device__ __align__(16) __half g_xh[(size_t)Tt * Ii * Bb]; // [t][i][b]
__device__ __align__(16) __half g_h1[2 * HB];
__device__ __align__(16) __half g_h2[2 * HB];
__device__ float g_c1[HB];
__device__ float g_c2[HB];
__device__ float g_b1[Gg];
__device__ float g_b2[Gg];
__device__ float g_bl[Oo];
__device__ unsigned g_bar;

// ---------------- single merged prep kernel ----------------
__global__ void prep_all(
    const float* __restrict__ x,
    const float* __restrict__ Wih1, const float* __restrict__ Whh1,
    const float* __restrict__ bi1,  const float* __restrict__ bh1,
    const float* __restrict__ Wih2, const float* __restrict__ Whh2,
    const float* __restrict__ bi2,  const float* __restrict__ bh2,
    const float* __restrict__ Wl,   const float* __restrict__ bl)
{
    const size_t idx = (size_t)blockIdx.x * blockDim.x + threadIdx.x;

    if (idx < (size_t)Gg * K2) {                 // W2, permuted rows, cols [x|h1|h2]
        int r = (int)(idx / K2), k = (int)(idx - (size_t)r * K2);
        int u = r >> 2, gt = r & 3;
        int orow = gt * Hh + u;
        float v = (k < K1) ? Wih2[(size_t)orow * K1 + k]
                           : Whh2[(size_t)orow * Hh + (k - K1)];
        g_W2[idx] = __float2half(v);
    }
    if (idx < (size_t)Gg * K1) {                 // W1, permuted rows, cols [x|h1]
        int r = (int)(idx / K1), k = (int)(idx - (size_t)r * K1);
        int u = r >> 2, gt = r & 3;
        int orow = gt * Hh + u;
        float v = (k < Ii) ? Wih1[(size_t)orow * Ii + k]
                           : Whh1[(size_t)orow * Hh + (k - Ii)];
        g_W1[idx] = __float2half(v);
    }
    if (idx < (size_t)Oo * K1) g_Wl[idx] = __float2half(Wl[idx]);
    if (idx < (size_t)Tt * Ii * Bb) {            // x -> [t][i][b], dest-linear
        int t = (int)(idx / (Ii * Bb));
        int rem = (int)(idx - (size_t)t * (Ii * Bb));
        int i = rem >> 6, b = rem & 63;
        g_xh[idx] = __float2half(x[((size_t)b * Tt + t) * Ii + i]);
    }
    if (idx < 2 * HB) { g_h1[idx] = __float2half(0.f); g_h2[idx] = __float2half(0.f); }
    if (idx < HB) { g_c1[idx] = 0.f; g_c2[idx] = 0.f; }
    if (idx < Gg) {
        int u = (int)idx >> 2, gt = (int)idx & 3;
        g_b1[idx] = bi1[gt * Hh + u] + bh1[gt * Hh + u];
        g_b2[idx] = bi2[gt * Hh + u] + bh2[gt * Hh + u];
    }
    if (idx < Oo) g_bl[idx] = bl[idx];
    if (idx == 0) g_bar = 0u;
}

// ---------------- helpers ----------------
struct Seg { const __half* z; int chunks; int ca; };

__device__ __forceinline__ float sigf(float x) { return 1.f / (1.f + __expf(-x)); }

__device__ __forceinline__ void cp16(uint32_t s, const void* g, int ca) {
    if (ca) asm volatile("cp.async.ca.shared.global [%0], [%1], 16;\n" :: "r"(s), "l"(g));
    else    asm volatile("cp.async.cg.shared.global [%0], [%1], 16;\n" :: "r"(s), "l"(g));
}
__device__ __forceinline__ void cp_commit() { asm volatile("cp.async.commit_group;\n"); }
__device__ __forceinline__ void cp_wait1()  { asm volatile("cp.async.wait_group 1;\n"); }
__device__ __forceinline__ void cp_wait0()  { asm volatile("cp.async.wait_group 0;\n"); }

// fence-free grid barrier: all cross-CTA data is read through L2 (cp.async.cg),
// so release/acquire atomics suffice — no CCTL.IVALL L1 flush needed.
__device__ __forceinline__ void gbar(unsigned target) {
    __syncthreads();
    if (threadIdx.x == 0) {
        asm volatile("red.release.gpu.global.add.u32 [%0], %1;\n"
                     :: "l"(&g_bar), "r"(1u) : "memory");
        unsigned v;
        do {
            asm volatile("ld.acquire.gpu.global.u32 %0, [%1];\n"
                         : "=r"(v) : "l"(&g_bar) : "memory");
        } while (v < target);
    }
    __syncthreads();
}

// load one 64-k chunk (A: 32x64, B: 64x64) into stage buffers via cp.async
__device__ __forceinline__ void load_stage(
    const __half* __restrict__ W, int ldw, int wca, int j, const Seg segs[3],
    uint32_t sAaddr, uint32_t sBaddr, int tid)
{
    {
        int row = tid >> 3, s8 = (tid & 7) * 8;
        cp16(sAaddr + (uint32_t)(row * PAD + s8) * 2,
             W + (size_t)row * ldw + j * 64 + s8, wca);
    }
    int jj = j, s = 0;
    if (jj >= segs[0].chunks) { jj -= segs[0].chunks; s = 1; }
    if (s == 1 && jj >= segs[1].chunks) { jj -= segs[1].chunks; s = 2; }
    const __half* z = segs[s].z + (size_t)(jj * 64) * Bb;
    const int zca = segs[s].ca;
#pragma unroll
    for (int r = 0; r < 2; ++r) {
        int idx = tid + r * 256;
        int krow = idx >> 3, s8 = (idx & 7) * 8;
        cp16(sBaddr + (uint32_t)(krow * PAD + s8) * 2,
             z + (size_t)krow * Bb + s8, zca);
    }
}

// compute one 64-k chunk: 4 x (2 ldmatrix.x4 + 2 mma.m16n8k16) per warp
__device__ __forceinline__ void compute_chunk(
    uint32_t sAaddr, uint32_t sBaddr, float acc[2][4], int lane, int wm, int wn)
{
    const int r16 = lane & 15, cs = lane >> 4;
#pragma unroll
    for (int k16 = 0; k16 < 4; ++k16) {
        const int kb = k16 * 16;
        uint32_t aaddr = sAaddr + (uint32_t)((wm * 16 + r16) * PAD + kb + cs * 8) * 2;
        uint32_t baddr = sBaddr + (uint32_t)((kb + r16) * PAD + wn * 16 + cs * 8) * 2;
        unsigned a0, a1, a2, a3, b0, b1, b2, b3;
        asm volatile("ldmatrix.sync.aligned.m8n8.x4.shared.b16 {%0,%1,%2,%3}, [%4];\n"
                     : "=r"(a0), "=r"(a1), "=r"(a2), "=r"(a3) : "r"(aaddr));
        asm volatile("ldmatrix.sync.aligned.m8n8.x4.trans.shared.b16 {%0,%1,%2,%3}, [%4];\n"
                     : "=r"(b0), "=r"(b1), "=r"(b2), "=r"(b3) : "r"(baddr));
        asm volatile("mma.sync.aligned.m16n8k16.row.col.f32.f16.f16.f32 "
                     "{%0,%1,%2,%3}, {%4,%5,%6,%7}, {%8,%9}, {%0,%1,%2,%3};\n"
                     : "+f"(acc[0][0]), "+f"(acc[0][1]), "+f"(acc[0][2]), "+f"(acc[0][3])
                     : "r"(a0), "r"(a1), "r"(a2), "r"(a3), "r"(b0), "r"(b1));
        asm volatile("mma.sync.aligned.m16n8k16.row.col.f32.f16.f16.f32 "
                     "{%0,%1,%2,%3}, {%4,%5,%6,%7}, {%8,%9}, {%0,%1,%2,%3};\n"
                     : "+f"(acc[1][0]), "+f"(acc[1][1]), "+f"(acc[1][2]), "+f"(acc[1][3])
                     : "r"(a0), "r"(a1), "r"(a2), "r"(a3), "r"(b2), "r"(b3));
    }
}

// pipelined 32x64 GEMM over nch 64-k chunks
__device__ __forceinline__ void gemm_tile(
    const __half* __restrict__ W, int ldw, int wca, const Seg segs[3], int nch,
    float acc[2][4], int tid, const uint32_t sA_s[3], const uint32_t sB_s[3])
{
    const int lane = tid & 31, wid = tid >> 5;
    const int wm = wid & 1, wn = wid >> 1;
    // prologue: stages 0,1
    load_stage(W, ldw, wca, 0, segs, sA_s[0], sB_s[0], tid); cp_commit();
    if (1 < nch) load_stage(W, ldw, wca, 1, segs, sA_s[1], sB_s[1], tid);
    cp_commit();
    int st = 0;
    for (int j = 0; j < nch; ++j) {
        cp_wait1();
        __syncthreads();
        const int jn = j + 2;
        const int stn = (st + 2 >= 3) ? st - 1 : st + 2;
        if (jn < nch) load_stage(W, ldw, wca, jn, segs, sA_s[stn], sB_s[stn], tid);
        cp_commit();
        compute_chunk(sA_s[st], sB_s[st], acc, lane, wm, wn);
        st = (st == 2) ? 0 : st + 1;
    }
    cp_wait0();
}

// LSTM pointwise: rows are 4u+gate -> CTA owns 8 full units
__device__ __forceinline__ void epi_gates(
    float acc[2][4], int tid, int m0, const float* __restrict__ bias,
    float* __restrict__ cbuf, __half* __restrict__ hdst, float (*s_g)[66])
{
    const int wid = tid >> 5, lane = tid & 31;
    const int grp = lane >> 2, tig = lane & 3;
    const int wm = wid & 1, wn = wid >> 1;
    const int m = wm * 16 + grp;
    __syncthreads();   // s_g aliases stage smem; ensure all gemm reads done
#pragma unroll
    for (int nt = 0; nt < 2; ++nt) {
        const int n = wn * 16 + nt * 8 + tig * 2;
        s_g[m][n] = acc[nt][0];      s_g[m][n + 1] = acc[nt][1];
        s_g[m + 8][n] = acc[nt][2];  s_g[m + 8][n + 1] = acc[nt][3];
    }
    __syncthreads();
    const int u0 = m0 >> 2;
#pragma unroll
    for (int j = 0; j < 2; ++j) {
        const int pi = tid + j * 256;
        const int du = pi >> 6, b = pi & 63;
        float ig = s_g[4 * du + 0][b] + bias[m0 + 4 * du + 0];
        float fg = s_g[4 * du + 1][b] + bias[m0 + 4 * du + 1];
        float gg = s_g[4 * du + 2][b] + bias[m0 + 4 * du + 2];
        float og = s_g[4 * du + 3][b] + bias[m0 + 4 * du + 3];
        const int ci = (u0 + du) * Bb + b;
        float c = cbuf[ci];
        float cn = sigf(fg) * c + sigf(ig) * tanhf(gg);
        cbuf[ci] = cn;
        hdst[ci] = __float2half(sigf(og) * tanhf(cn));
    }
    __syncthreads();   // protect aliased smem before next gemm's prologue loads
}

__device__ __forceinline__ void do_y(
    int tile, int t_y, int p, float* __restrict__ out, int tid,
    const uint32_t sA_s[3], const uint32_t sB_s[3])
{
    const int m0 = (tile - 128) * 32;
    float acc[2][4] = {{0.f,0.f,0.f,0.f},{0.f,0.f,0.f,0.f}};
    Seg segs[3] = { { g_xh + (size_t)t_y * (Ii * Bb), Ii / 64, 1 },
                    { g_h2 + (size_t)p * HB, Hh / 64, 0 },
                    { nullptr, 0, 0 } };
    gemm_tile(g_Wl + (size_t)m0 * K1, K1, 1, segs, K1 / 64, acc, tid, sA_s, sB_s);
    const int wid = tid >> 5, lane = tid & 31;
    const int grp = lane >> 2, tig = lane & 3;
    const int wm = wid & 1, wn = wid >> 1;
    const int m = m0 + wm * 16 + grp;
#pragma unroll
    for (int nt = 0; nt < 2; ++nt) {
        const int n = wn * 16 + nt * 8 + tig * 2;   // batch
        const size_t r0 = (size_t)n * (Tt * Oo) + (size_t)t_y * Oo;
        const size_t r1 = (size_t)(n + 1) * (Tt * Oo) + (size_t)t_y * Oo;
        out[r0 + m]     = acc[nt][0] + g_bl[m];
        out[r1 + m]     = acc[nt][1] + g_bl[m];
        out[r0 + m + 8] = acc[nt][2] + g_bl[m + 8];
        out[r1 + m + 8] = acc[nt][3] + g_bl[m + 8];
    }
    __syncthreads();
}

// ---------------- persistent LSTM kernel ----------------
__global__ void __launch_bounds__(NTHR, 1) lstm_main(float* __restrict__ out) {
    __shared__ __align__(16) __half sA[3][32][PAD];
    __shared__ __align__(16) __half sB[3][64][PAD];
    float (*s_g)[66] = reinterpret_cast<float(*)[66]>(&sA[0][0][0]); // alias (fenced)

    uint32_t sA_s[3], sB_s[3];
#pragma unroll
    for (int s = 0; s < 3; ++s) {
        sA_s[s] = (uint32_t)__cvta_generic_to_shared(&sA[s][0][0]);
        sB_s[s] = (uint32_t)__cvta_generic_to_shared(&sB[s][0][0]);
    }
    const int tile = blockIdx.x;
    const int tid = threadIdx.x;
    unsigned ph = 0;

    for (int t = 0; t <= Tt; ++t) {
        const int p = t & 1;
        // ---- Phase A: gates1(t) on tiles 0..127 ; y(t-1) on tiles 128..135
        if (t < Tt) {
            if (tile < 128) {
                const int m0 = tile * 32;
                float acc[2][4] = {{0.f,0.f,0.f,0.f},{0.f,0.f,0.f,0.f}};
                Seg segs[3] = { { g_xh + (size_t)t * (Ii * Bb), Ii / 64, 1 },
                                { g_h1 + (size_t)(1 - p) * HB, Hh / 64, 0 },
                                { nullptr, 0, 0 } };
                gemm_tile(g_W1 + (size_t)m0 * K1, K1, 1, segs, K1 / 64, acc,
                          tid, sA_s, sB_s);
                epi_gates(acc, tid, m0, g_b1, g_c1, g_h1 + (size_t)p * HB, s_g);
            } else if (t > 0) {
                do_y(tile, t - 1, p, out, tid, sA_s, sB_s);
            }
        } else {
            if (tile >= 128) do_y(tile, t - 1, p, out, tid, sA_s, sB_s);
            break;
        }
        ph++; gbar(ph * NBLK);
        // ---- Phase B: gates2(t) on tiles 0..127
        if (tile < 128) {
            const int m0 = tile * 32;
            float acc[2][4] = {{0.f,0.f,0.f,0.f},{0.f,0.f,0.f,0.f}};
            Seg segs[3] = { { g_xh + (size_t)t * (Ii * Bb), Ii / 64, 1 },
                            { g_h1 + (size_t)p * HB, Hh / 64, 0 },
                            { g_h2 + (size_t)p * HB, Hh / 64, 0 } };
            gemm_tile(g_W2 + (size_t)m0 * K2, K2, 0, segs, K2 / 64, acc,
                      tid, sA_s, sB_s);
            epi_gates(acc, tid, m0, g_b2, g_c2, g_h2 + (size_t)(1 - p) * HB, s_g);
        }
        ph++; gbar(ph * NBLK);
    }
}

// ---------------- launch ----------------
extern "C" void kernel_launch(void* const* d_in, const int* in_sizes, int n_in,
                              void* d_out, int out_size) {
    const float* x    = (const float*)d_in[0];
    const float* Wih1 = (const float*)d_in[1];
    const float* Whh1 = (const float*)d_in[2];
    const float* bih1 = (const float*)d_in[3];
    const float* bhh1 = (const float*)d_in[4];
    const float* Wih2 = (const float*)d_in[5];
    const float* Whh2 = (const float*)d_in[6];
    const float* bih2 = (const float*)d_in[7];
    const float* bhh2 = (const float*)d_in[8];
    const float* Wl   = (const float*)d_in[9];
    const float* bl   = (const float*)d_in[10];
    float* out = (float*)d_out;

    const size_t nprep = (size_t)Gg * K2;
    prep_all<<<(unsigned)((nprep + 255) / 256), 256>>>(
        x, Wih1, Whh1, bih1, bhh1, Wih2, Whh2, bih2, bhh2, Wl, bl);
    lstm_main<<<NBLK, NTHR>>>(out);
}

// round 6
// speedup vs baseline: 1.6142x; 1.0392x over previous
#include <cuda_runtime.h>
#include <cuda_fp16.h>
#include <cstdint>

#define Bb   64
#define Tt   256
#define Ii   256
#define Hh   1024
#define Gg   4096
#define Oo   256
#define K1   1280          // I + H
#define K2   2304          // I + H + H
#define NBLK 136
#define NTHR 256
#define HB   (Hh * Bb)     // 65536
#define PAD  72            // smem row padding (halves); 144B stride -> conflict-free ldmatrix
#define STG  5             // pipeline stages
#define STRIDE_ST ((32 + 64) * PAD)          // halves per stage (A + B)
#define SMEM_BYTES (STG * STRIDE_ST * 2)     // 69120 B

// ---------------- device-global scratch ----------------
__device__ __align__(16) __half g_W1[(size_t)Gg * K1];
__device__ __align__(16) __half g_W2[(size_t)Gg * K2];
__device__ __align__(16) __half g_Wl[(size_t)Oo * K1];
__device__ __align__(16) __half g_xh[(size_t)Tt * Ii * Bb]; // [t][i][b]
__device__ __align__(16) __half g_h1[2 * HB];
__device__ __align__(16) __half g_h2[2 * HB];
__device__ float g_c1[HB];
__device__ float g_c2[HB];
__device__ float g_b1[Gg];
__device__ float g_b2[Gg];
__device__ float g_bl[Oo];
__device__ unsigned g_bar;

// ---------------- single merged prep kernel ----------------
__global__ void prep_all(
    const float* __restrict__ x,
    const float* __restrict__ Wih1, const float* __restrict__ Whh1,
    const float* __restrict__ bi1,  const float* __restrict__ bh1,
    const float* __restrict__ Wih2, const float* __restrict__ Whh2,
    const float* __restrict__ bi2,  const float* __restrict__ bh2,
    const float* __restrict__ Wl,   const float* __restrict__ bl)
{
    const size_t idx = (size_t)blockIdx.x * blockDim.x + threadIdx.x;

    if (idx < (size_t)Gg * K2) {                 // W2, permuted rows, cols [x|h1|h2]
        int r = (int)(idx / K2), k = (int)(idx - (size_t)r * K2);
        int u = r >> 2, gt = r & 3;
        int orow = gt * Hh + u;
        float v = (k < K1) ? Wih2[(size_t)orow * K1 + k]
                           : Whh2[(size_t)orow * Hh + (k - K1)];
        g_W2[idx] = __float2half(v);
    }
    if (idx < (size_t)Gg * K1) {                 // W1, permuted rows, cols [x|h1]
        int r = (int)(idx / K1), k = (int)(idx - (size_t)r * K1);
        int u = r >> 2, gt = r & 3;
        int orow = gt * Hh + u;
        float v = (k < Ii) ? Wih1[(size_t)orow * Ii + k]
                           : Whh1[(size_t)orow * Hh + (k - Ii)];
        g_W1[idx] = __float2half(v);
    }
    if (idx < (size_t)Oo * K1) g_Wl[idx] = __float2half(Wl[idx]);
    if (idx < (size_t)Tt * Ii * Bb) {            // x -> [t][i][b], dest-linear
        int t = (int)(idx / (Ii * Bb));
        int rem = (int)(idx - (size_t)t * (Ii * Bb));
        int i = rem >> 6, b = rem & 63;
        g_xh[idx] = __float2half(x[((size_t)b * Tt + t) * Ii + i]);
    }
    if (idx < 2 * HB) { g_h1[idx] = __float2half(0.f); g_h2[idx] = __float2half(0.f); }
    if (idx < HB) { g_c1[idx] = 0.f; g_c2[idx] = 0.f; }
    if (idx < Gg) {
        int u = (int)idx >> 2, gt = (int)idx & 3;
        g_b1[idx] = bi1[gt * Hh + u] + bh1[gt * Hh + u];
        g_b2[idx] = bi2[gt * Hh + u] + bh2[gt * Hh + u];
    }
    if (idx < Oo) g_bl[idx] = bl[idx];
    if (idx == 0) g_bar = 0u;
}

// ---------------- helpers ----------------
struct Seg { const __half* z; int chunks; int ca; };

__device__ __forceinline__ float sigf(float x) { return 1.f / (1.f + __expf(-x)); }

__device__ __forceinline__ void cp16(uint32_t s, const void* g, int ca) {
    if (ca) asm volatile("cp.async.ca.shared.global [%0], [%1], 16;\n" :: "r"(s), "l"(g));
    else    asm volatile("cp.async.cg.shared.global [%0], [%1], 16;\n" :: "r"(s), "l"(g));
}
__device__ __forceinline__ void cp_commit() { asm volatile("cp.async.commit_group;\n"); }
__device__ __forceinline__ void cp_wait3()  { asm volatile("cp.async.wait_group 3;\n"); }
__device__ __forceinline__ void cp_wait0()  { asm volatile("cp.async.wait_group 0;\n"); }

// fence-free grid barrier: all cross-CTA data (h1/h2) is read via cp.async.cg
// (L1-bypass; L2 is the coherence point) -> release/acquire atomics suffice,
// no CCTL.IVALL L1 flush (which would evict the L1-resident W2 slice!).
__device__ __forceinline__ void gbar(unsigned target) {
    __syncthreads();
    if (threadIdx.x == 0) {
        asm volatile("red.release.gpu.global.add.u32 [%0], %1;\n"
                     :: "l"(&g_bar), "r"(1u) : "memory");
        unsigned v;
        do {
            asm volatile("ld.acquire.gpu.global.u32 %0, [%1];\n"
                         : "=r"(v) : "l"(&g_bar) : "memory");
        } while (v < target);
    }
    __syncthreads();
}

// load one 64-k chunk (A: 32x64, B: 64x64) into a stage via cp.async
__device__ __forceinline__ void load_stage(
    const __half* __restrict__ W, int ldw, int wca, int j, const Seg segs[3],
    uint32_t sAaddr, uint32_t sBaddr, int tid)
{
    {
        int row = tid >> 3, s8 = (tid & 7) * 8;
        cp16(sAaddr + (uint32_t)(row * PAD + s8) * 2,
             W + (size_t)row * ldw + j * 64 + s8, wca);
    }
    int jj = j, s = 0;
    if (jj >= segs[0].chunks) { jj -= segs[0].chunks; s = 1; }
    if (s == 1 && jj >= segs[1].chunks) { jj -= segs[1].chunks; s = 2; }
    const __half* z = segs[s].z + (size_t)(jj * 64) * Bb;
    const int zca = segs[s].ca;
#pragma unroll
    for (int r = 0; r < 2; ++r) {
        int idx = tid + r * 256;
        int krow = idx >> 3, s8 = (idx & 7) * 8;
        cp16(sBaddr + (uint32_t)(krow * PAD + s8) * 2,
             z + (size_t)krow * Bb + s8, zca);
    }
}

// compute one 64-k chunk: 4 x (2 ldmatrix.x4 + 2 mma.m16n8k16) per warp
__device__ __forceinline__ void compute_chunk(
    uint32_t sAaddr, uint32_t sBaddr, float acc[2][4], int lane, int wm, int wn)
{
    const int r16 = lane & 15, cs = lane >> 4;
#pragma unroll
    for (int k16 = 0; k16 < 4; ++k16) {
        const int kb = k16 * 16;
        uint32_t aaddr = sAaddr + (uint32_t)((wm * 16 + r16) * PAD + kb + cs * 8) * 2;
        uint32_t baddr = sBaddr + (uint32_t)((kb + r16) * PAD + wn * 16 + cs * 8) * 2;
        unsigned a0, a1, a2, a3, b0, b1, b2, b3;
        asm volatile("ldmatrix.sync.aligned.m8n8.x4.shared.b16 {%0,%1,%2,%3}, [%4];\n"
                     : "=r"(a0), "=r"(a1), "=r"(a2), "=r"(a3) : "r"(aaddr));
        asm volatile("ldmatrix.sync.aligned.m8n8.x4.trans.shared.b16 {%0,%1,%2,%3}, [%4];\n"
                     : "=r"(b0), "=r"(b1), "=r"(b2), "=r"(b3) : "r"(baddr));
        asm volatile("mma.sync.aligned.m16n8k16.row.col.f32.f16.f16.f32 "
                     "{%0,%1,%2,%3}, {%4,%5,%6,%7}, {%8,%9}, {%0,%1,%2,%3};\n"
                     : "+f"(acc[0][0]), "+f"(acc[0][1]), "+f"(acc[0][2]), "+f"(acc[0][3])
                     : "r"(a0), "r"(a1), "r"(a2), "r"(a3), "r"(b0), "r"(b1));
        asm volatile("mma.sync.aligned.m16n8k16.row.col.f32.f16.f16.f32 "
                     "{%0,%1,%2,%3}, {%4,%5,%6,%7}, {%8,%9}, {%0,%1,%2,%3};\n"
                     : "+f"(acc[1][0]), "+f"(acc[1][1]), "+f"(acc[1][2]), "+f"(acc[1][3])
                     : "r"(a0), "r"(a1), "r"(a2), "r"(a3), "r"(b2), "r"(b3));
    }
}

// 5-stage pipelined 32x64 GEMM over nch 64-k chunks (wait_group 3)
__device__ __forceinline__ void gemm_tile(
    const __half* __restrict__ W, int ldw, int wca, const Seg segs[3], int nch,
    float acc[2][4], int tid, const uint32_t sA_s[STG], const uint32_t sB_s[STG])
{
    const int lane = tid & 31, wid = tid >> 5;
    const int wm = wid & 1, wn = wid >> 1;
#pragma unroll
    for (int j0 = 0; j0 < STG - 1; ++j0) {       // prologue: 4 chunks in flight
        if (j0 < nch) load_stage(W, ldw, wca, j0, segs, sA_s[j0], sB_s[j0], tid);
        cp_commit();
    }
    int st = 0, stn = STG - 1;
    for (int j = 0; j < nch; ++j) {
        cp_wait3();                // group j complete (<=3 younger pending)
        __syncthreads();
        const int jn = j + (STG - 1);
        if (jn < nch) load_stage(W, ldw, wca, jn, segs, sA_s[stn], sB_s[stn], tid);
        cp_commit();
        compute_chunk(sA_s[st], sB_s[st], acc, lane, wm, wn);
        st  = (st  == STG - 1) ? 0 : st  + 1;
        stn = (stn == STG - 1) ? 0 : stn + 1;
    }
    cp_wait0();
}

// LSTM pointwise: rows are 4u+gate -> CTA owns 8 full units
__device__ __forceinline__ void epi_gates(
    float acc[2][4], int tid, int m0, const float* __restrict__ bias,
    float* __restrict__ cbuf, __half* __restrict__ hdst, float (*s_g)[66])
{
    const int wid = tid >> 5, lane = tid & 31;
    const int grp = lane >> 2, tig = lane & 3;
    const int wm = wid & 1, wn = wid >> 1;
    const int m = wm * 16 + grp;
    __syncthreads();   // s_g aliases stage smem; ensure all gemm reads done
#pragma unroll
    for (int nt = 0; nt < 2; ++nt) {
        const int n = wn * 16 + nt * 8 + tig * 2;
        s_g[m][n] = acc[nt][0];      s_g[m][n + 1] = acc[nt][1];
        s_g[m + 8][n] = acc[nt][2];  s_g[m + 8][n + 1] = acc[nt][3];
    }
    __syncthreads();
    const int u0 = m0 >> 2;
#pragma unroll
    for (int j = 0; j < 2; ++j) {
        const int pi = tid + j * 256;
        const int du = pi >> 6, b = pi & 63;
        float ig = s_g[4 * du + 0][b] + bias[m0 + 4 * du + 0];
        float fg = s_g[4 * du + 1][b] + bias[m0 + 4 * du + 1];
        float gg = s_g[4 * du + 2][b] + bias[m0 + 4 * du + 2];
        float og = s_g[4 * du + 3][b] + bias[m0 + 4 * du + 3];
        const int ci = (u0 + du) * Bb + b;
        float c = cbuf[ci];
        float cn = sigf(fg) * c + sigf(ig) * tanhf(gg);
        cbuf[ci] = cn;
        hdst[ci] = __float2half(sigf(og) * tanhf(cn));
    }
    __syncthreads();   // protect aliased smem before next gemm's prologue loads
}

__device__ __forceinline__ void do_y(
    int tile, int t_y, int p, float* __restrict__ out, int tid,
    const uint32_t sA_s[STG], const uint32_t sB_s[STG])
{
    const int m0 = (tile - 128) * 32;
    float acc[2][4] = {{0.f,0.f,0.f,0.f},{0.f,0.f,0.f,0.f}};
    Seg segs[3] = { { g_xh + (size_t)t_y * (Ii * Bb), Ii / 64, 0 },
                    { g_h2 + (size_t)p * HB, Hh / 64, 0 },
                    { nullptr, 0, 0 } };
    gemm_tile(g_Wl + (size_t)m0 * K1, K1, 1, segs, K1 / 64, acc, tid, sA_s, sB_s);
    const int wid = tid >> 5, lane = tid & 31;
    const int grp = lane >> 2, tig = lane & 3;
    const int wm = wid & 1, wn = wid >> 1;
    const int m = m0 + wm * 16 + grp;
#pragma unroll
    for (int nt = 0; nt < 2; ++nt) {
        const int n = wn * 16 + nt * 8 + tig * 2;   // batch
        const size_t r0 = (size_t)n * (Tt * Oo) + (size_t)t_y * Oo;
        const size_t r1 = (size_t)(n + 1) * (Tt * Oo) + (size_t)t_y * Oo;
        out[r0 + m]     = acc[nt][0] + g_bl[m];
        out[r1 + m]     = acc[nt][1] + g_bl[m];
        out[r0 + m + 8] = acc[nt][2] + g_bl[m + 8];
        out[r1 + m + 8] = acc[nt][3] + g_bl[m + 8];
    }
    __syncthreads();
}

// ---------------- persistent LSTM kernel ----------------
// L1 policy: W2 slice (144KB) loaded with .ca -> stays L1-resident across all
// 256 steps (L1D = 228KB - 69KB smem = ~159KB; persistent launch keeps L1).
// Everything else (W1, x, h1, h2) uses .cg so it never evicts W2.
__global__ void __launch_bounds__(NTHR, 1) lstm_main(float* __restrict__ out) {
    extern __shared__ __align__(16) __half smem_dyn[];
    float (*s_g)[66] = reinterpret_cast<float(*)[66]>(smem_dyn);  // alias (fenced)

    uint32_t sA_s[STG], sB_s[STG];
    const uint32_t sbase = (uint32_t)__cvta_generic_to_shared(smem_dyn);
#pragma unroll
    for (int s = 0; s < STG; ++s) {
        sA_s[s] = sbase + (uint32_t)(s * STRIDE_ST) * 2;
        sB_s[s] = sA_s[s] + 32 * PAD * 2;
    }
    const int tile = blockIdx.x;
    const int tid = threadIdx.x;
    unsigned ph = 0;

    for (int t = 0; t <= Tt; ++t) {
        const int p = t & 1;
        // ---- Phase A: gates1(t) on tiles 0..127 ; y(t-1) on tiles 128..135
        if (t < Tt) {
            if (tile < 128) {
                const int m0 = tile * 32;
                float acc[2][4] = {{0.f,0.f,0.f,0.f},{0.f,0.f,0.f,0.f}};
                Seg segs[3] = { { g_xh + (size_t)t * (Ii * Bb), Ii / 64, 0 },
                                { g_h1 + (size_t)(1 - p) * HB, Hh / 64, 0 },
                                { nullptr, 0, 0 } };
                gemm_tile(g_W1 + (size_t)m0 * K1, K1, 0, segs, K1 / 64, acc,
                          tid, sA_s, sB_s);
                epi_gates(acc, tid, m0, g_b1, g_c1, g_h1 + (size_t)p * HB, s_g);
            } else if (t > 0) {
                do_y(tile, t - 1, p, out, tid, sA_s, sB_s);
            }
        } else {
            if (tile >= 128) do_y(tile, t - 1, p, out, tid, sA_s, sB_s);
            break;
        }
        ph++; gbar(ph * NBLK);
        // ---- Phase B: gates2(t) on tiles 0..127  (W2 via .ca -> L1-resident)
        if (tile < 128) {
            const int m0 = tile * 32;
            float acc[2][4] = {{0.f,0.f,0.f,0.f},{0.f,0.f,0.f,0.f}};
            Seg segs[3] = { { g_xh + (size_t)t * (Ii * Bb), Ii / 64, 0 },
                            { g_h1 + (size_t)p * HB, Hh / 64, 0 },
                            { g_h2 + (size_t)p * HB, Hh / 64, 0 } };
            gemm_tile(g_W2 + (size_t)m0 * K2, K2, 1, segs, K2 / 64, acc,
                      tid, sA_s, sB_s);
            epi_gates(acc, tid, m0, g_b2, g_c2, g_h2 + (size_t)(1 - p) * HB, s_g);
        }
        ph++; gbar(ph * NBLK);
    }
}

// ---------------- launch ----------------
extern "C" void kernel_launch(void* const* d_in, const int* in_sizes, int n_in,
                              void* d_out, int out_size) {
    const float* x    = (const float*)d_in[0];
    const float* Wih1 = (const float*)d_in[1];
    const float* Whh1 = (const float*)d_in[2];
    const float* bih1 = (const float*)d_in[3];
    const float* bhh1 = (const float*)d_in[4];
    const float* Wih2 = (const float*)d_in[5];
    const float* Whh2 = (const float*)d_in[6];
    const float* bih2 = (const float*)d_in[7];
    const float* bhh2 = (const float*)d_in[8];
    const float* Wl   = (const float*)d_in[9];
    const float* bl   = (const float*)d_in[10];
    float* out = (float*)d_out;

    cudaFuncSetAttribute(lstm_main, cudaFuncAttributeMaxDynamicSharedMemorySize,
                         SMEM_BYTES);

    const size_t nprep = (size_t)Gg * K2;
    prep_all<<<(unsigned)((nprep + 255) / 256), 256>>>(
        x, Wih1, Whh1, bih1, bhh1, Wih2, Whh2, bih2, bhh2, Wl, bl);
    lstm_main<<<NBLK, NTHR, SMEM_BYTES>>>(out);
}

// round 7
// speedup vs baseline: 1.6683x; 1.0335x over previous
#include <cuda_runtime.h>
#include <cuda_fp16.h>
#include <cstdint>

#define Bb   64
#define Tt   256
#define Ii   256
#define Hh   1024
#define Gg   4096
#define Oo   256
#define K1   1280          // I + H
#define K2   2304          // I + H + H
#define NBLK 136
#define NTHR 512
#define HB   (Hh * Bb)     // 65536
#define CH   128           // k per chunk
#define APAD 136           // A smem row stride (halves): 272B -> conflict-free ldmatrix
#define BPAD 72            // B smem row stride (halves): 144B -> conflict-free ldmatrix
#define A_ST (32 * APAD)                      // 4352 halves
#define B_ST (CH * BPAD)                      // 9216 halves
#define STRIDE_ST (A_ST + B_ST)               // 13568 halves / stage
#define STG  4
#define SMEM_BYTES (STG * STRIDE_ST * 2)      // 108544 B

// ---------------- device-global scratch ----------------
__device__ __align__(16) __half g_W1[(size_t)Gg * K1];
__device__ __align__(16) __half g_W2[(size_t)Gg * K2];
__device__ __align__(16) __half g_Wl[(size_t)Oo * K1];
__device__ __align__(16) __half g_xh[(size_t)Tt * Ii * Bb]; // [t][i][b]
__device__ __align__(16) __half g_h1[2 * HB];
__device__ __align__(16) __half g_h2[2 * HB];
__device__ float g_c1[HB];
__device__ float g_c2[HB];
__device__ float g_b1[Gg];
__device__ float g_b2[Gg];
__device__ float g_bl[Oo];
__device__ unsigned g_bar;

// ---------------- single merged prep kernel ----------------
__global__ void prep_all(
    const float* __restrict__ x,
    const float* __restrict__ Wih1, const float* __restrict__ Whh1,
    const float* __restrict__ bi1,  const float* __restrict__ bh1,
    const float* __restrict__ Wih2, const float* __restrict__ Whh2,
    const float* __restrict__ bi2,  const float* __restrict__ bh2,
    const float* __restrict__ Wl,   const float* __restrict__ bl)
{
    const size_t idx = (size_t)blockIdx.x * blockDim.x + threadIdx.x;

    if (idx < (size_t)Gg * K2) {                 // W2, permuted rows, cols [x|h1|h2]
        int r = (int)(idx / K2), k = (int)(idx - (size_t)r * K2);
        int u = r >> 2, gt = r & 3;
        int orow = gt * Hh + u;
        float v = (k < K1) ? Wih2[(size_t)orow * K1 + k]
                           : Whh2[(size_t)orow * Hh + (k - K1)];
        g_W2[idx] = __float2half(v);
    }
    if (idx < (size_t)Gg * K1) {                 // W1, permuted rows, cols [x|h1]
        int r = (int)(idx / K1), k = (int)(idx - (size_t)r * K1);
        int u = r >> 2, gt = r & 3;
        int orow = gt * Hh + u;
        float v = (k < Ii) ? Wih1[(size_t)orow * Ii + k]
                           : Whh1[(size_t)orow * Hh + (k - Ii)];
        g_W1[idx] = __float2half(v);
    }
    if (idx < (size_t)Oo * K1) g_Wl[idx] = __float2half(Wl[idx]);
    if (idx < (size_t)Tt * Ii * Bb) {            // x -> [t][i][b], dest-linear
        int t = (int)(idx / (Ii * Bb));
        int rem = (int)(idx - (size_t)t * (Ii * Bb));
        int i = rem >> 6, b = rem & 63;
        g_xh[idx] = __float2half(x[((size_t)b * Tt + t) * Ii + i]);
    }
    if (idx < 2 * HB) { g_h1[idx] = __float2half(0.f); g_h2[idx] = __float2half(0.f); }
    if (idx < HB) { g_c1[idx] = 0.f; g_c2[idx] = 0.f; }
    if (idx < Gg) {
        int u = (int)idx >> 2, gt = (int)idx & 3;
        g_b1[idx] = bi1[gt * Hh + u] + bh1[gt * Hh + u];
        g_b2[idx] = bi2[gt * Hh + u] + bh2[gt * Hh + u];
    }
    if (idx < Oo) g_bl[idx] = bl[idx];
    if (idx == 0) g_bar = 0u;
}

// ---------------- helpers ----------------
struct Seg { const __half* z; int chunks; };

__device__ __forceinline__ float sigf(float x) { return 1.f / (1.f + __expf(-x)); }

__device__ __forceinline__ void cp16(uint32_t s, const void* g, int ca) {
    if (ca) asm volatile("cp.async.ca.shared.global [%0], [%1], 16;\n" :: "r"(s), "l"(g));
    else    asm volatile("cp.async.cg.shared.global [%0], [%1], 16;\n" :: "r"(s), "l"(g));
}
__device__ __forceinline__ void cp_commit() { asm volatile("cp.async.commit_group;\n"); }
__device__ __forceinline__ void cp_wait2()  { asm volatile("cp.async.wait_group 2;\n"); }
__device__ __forceinline__ void cp_wait0()  { asm volatile("cp.async.wait_group 0;\n"); }

// fence-free grid barrier: all cross-CTA data (h1/h2) is read via cp.async.cg
// (L1-bypass; L2 is the coherence point) -> release/acquire atomics suffice.
__device__ __forceinline__ void gbar(unsigned target) {
    __syncthreads();
    if (threadIdx.x == 0) {
        asm volatile("red.release.gpu.global.add.u32 [%0], %1;\n"
                     :: "l"(&g_bar), "r"(1u) : "memory");
        unsigned v;
        do {
            asm volatile("ld.acquire.gpu.global.u32 %0, [%1];\n"
                         : "=r"(v) : "l"(&g_bar) : "memory");
        } while (v < target);
    }
    __syncthreads();
}

// load one 128-k chunk (A: 32x128, B: 128x64) into a stage via cp.async
__device__ __forceinline__ void load_stage(
    const __half* __restrict__ W, int ldw, int wca, int j, const Seg segs[3],
    uint32_t sAaddr, uint32_t sBaddr, int tid)
{
    {   // A: 32 rows x 128 halves; 512 x 16B ops, 1 per thread
        int row = tid >> 4, seg = tid & 15;
        cp16(sAaddr + (uint32_t)(row * APAD + seg * 8) * 2,
             W + (size_t)row * ldw + j * CH + seg * 8, wca);
    }
    int jj = j, s = 0;
    if (jj >= segs[0].chunks) { jj -= segs[0].chunks; s = 1; }
    if (s == 1 && jj >= segs[1].chunks) { jj -= segs[1].chunks; s = 2; }
    const __half* z = segs[s].z + (size_t)jj * CH * Bb;
#pragma unroll
    for (int r = 0; r < 2; ++r) {   // B: 128 k-rows x 64 halves; 1024 ops
        int idx = tid + r * NTHR;
        int krow = idx >> 3, seg = idx & 7;
        cp16(sBaddr + (uint32_t)(krow * BPAD + seg * 8) * 2,
             z + (size_t)krow * Bb + seg * 8, 0);
    }
}

// compute one 128-k chunk: warp tile 16m x 8n; 8 x (ldmatrix.x4 + ldmatrix.x2 + mma)
__device__ __forceinline__ void compute_chunk(
    uint32_t sAaddr, uint32_t sBaddr, float acc[4], int lane, int wm, int wn)
{
    const int r16 = lane & 15, cs = lane >> 4;
    const int bl8 = lane & 7, bm = (lane >> 3) & 1;
#pragma unroll
    for (int k16 = 0; k16 < 8; ++k16) {
        const int kb = k16 * 16;
        uint32_t aaddr = sAaddr + (uint32_t)((wm * 16 + r16) * APAD + kb + cs * 8) * 2;
        uint32_t baddr = sBaddr + (uint32_t)((kb + bl8 + 8 * bm) * BPAD + wn * 8) * 2;
        unsigned a0, a1, a2, a3, b0, b1;
        asm volatile("ldmatrix.sync.aligned.m8n8.x4.shared.b16 {%0,%1,%2,%3}, [%4];\n"
                     : "=r"(a0), "=r"(a1), "=r"(a2), "=r"(a3) : "r"(aaddr));
        asm volatile("ldmatrix.sync.aligned.m8n8.x2.trans.shared.b16 {%0,%1}, [%2];\n"
                     : "=r"(b0), "=r"(b1) : "r"(baddr));
        asm volatile("mma.sync.aligned.m16n8k16.row.col.f32.f16.f16.f32 "
                     "{%0,%1,%2,%3}, {%4,%5,%6,%7}, {%8,%9}, {%0,%1,%2,%3};\n"
                     : "+f"(acc[0]), "+f"(acc[1]), "+f"(acc[2]), "+f"(acc[3])
                     : "r"(a0), "r"(a1), "r"(a2), "r"(a3), "r"(b0), "r"(b1));
    }
}

// 4-stage pipelined 32x64 GEMM over nch 128-k chunks (wait_group 2)
__device__ __forceinline__ void gemm_tile(
    const __half* __restrict__ W, int ldw, int wca, const Seg segs[3], int nch,
    float acc[4], int tid, const uint32_t sA_s[STG], const uint32_t sB_s[STG])
{
    const int lane = tid & 31, wid = tid >> 5;
    const int wm = wid & 1, wn = wid >> 1;
#pragma unroll
    for (int j0 = 0; j0 < STG - 1; ++j0) {       // prologue: 3 chunks in flight
        if (j0 < nch) load_stage(W, ldw, wca, j0, segs, sA_s[j0], sB_s[j0], tid);
        cp_commit();
    }
    int st = 0, stn = STG - 1;
    for (int j = 0; j < nch; ++j) {
        cp_wait2();                // group j complete (<=2 younger pending)
        __syncthreads();
        const int jn = j + (STG - 1);
        if (jn < nch) load_stage(W, ldw, wca, jn, segs, sA_s[stn], sB_s[stn], tid);
        cp_commit();
        compute_chunk(sA_s[st], sB_s[st], acc, lane, wm, wn);
        st  = (st  == STG - 1) ? 0 : st  + 1;
        stn = (stn == STG - 1) ? 0 : stn + 1;
    }
    cp_wait0();
}

// LSTM pointwise: rows are 4u+gate -> CTA owns 8 full units (512 cells)
__device__ __forceinline__ void epi_gates(
    float acc[4], int tid, int m0, const float* __restrict__ bias,
    float* __restrict__ cbuf, __half* __restrict__ hdst, float (*s_g)[66])
{
    const int wid = tid >> 5, lane = tid & 31;
    const int grp = lane >> 2, tig = lane & 3;
    const int wm = wid & 1, wn = wid >> 1;
    const int m = wm * 16 + grp;
    const int n = wn * 8 + tig * 2;
    __syncthreads();   // s_g aliases stage smem; ensure all gemm reads done
    s_g[m][n] = acc[0];      s_g[m][n + 1] = acc[1];
    s_g[m + 8][n] = acc[2];  s_g[m + 8][n + 1] = acc[3];
    __syncthreads();
    const int u0 = m0 >> 2;
    {
        const int du = tid >> 6, b = tid & 63;   // 512 threads = 8 units x 64 b
        float ig = s_g[4 * du + 0][b] + bias[m0 + 4 * du + 0];
        float fg = s_g[4 * du + 1][b] + bias[m0 + 4 * du + 1];
        float gg = s_g[4 * du + 2][b] + bias[m0 + 4 * du + 2];
        float og = s_g[4 * du + 3][b] + bias[m0 + 4 * du + 3];
        const int ci = (u0 + du) * Bb + b;
        float c = cbuf[ci];
        float cn = sigf(fg) * c + sigf(ig) * tanhf(gg);
        cbuf[ci] = cn;
        hdst[ci] = __float2half(sigf(og) * tanhf(cn));
    }
    __syncthreads();   // protect aliased smem before next gemm's prologue loads
}

__device__ __forceinline__ void do_y(
    int tile, int t_y, int p, float* __restrict__ out, int tid,
    const uint32_t sA_s[STG], const uint32_t sB_s[STG])
{
    const int m0 = (tile - 128) * 32;
    float acc[4] = {0.f, 0.f, 0.f, 0.f};
    Seg segs[3] = { { g_xh + (size_t)t_y * (Ii * Bb), Ii / CH },
                    { g_h2 + (size_t)p * HB, Hh / CH },
                    { nullptr, 0 } };
    gemm_tile(g_Wl + (size_t)m0 * K1, K1, 1, segs, K1 / CH, acc, tid, sA_s, sB_s);
    const int wid = tid >> 5, lane = tid & 31;
    const int grp = lane >> 2, tig = lane & 3;
    const int wm = wid & 1, wn = wid >> 1;
    const int m = m0 + wm * 16 + grp;
    const int n = wn * 8 + tig * 2;   // batch
    const size_t r0 = (size_t)n * (Tt * Oo) + (size_t)t_y * Oo;
    const size_t r1 = (size_t)(n + 1) * (Tt * Oo) + (size_t)t_y * Oo;
    out[r0 + m]     = acc[0] + g_bl[m];
    out[r1 + m]     = acc[1] + g_bl[m];
    out[r0 + m + 8] = acc[2] + g_bl[m + 8];
    out[r1 + m + 8] = acc[3] + g_bl[m + 8];
    __syncthreads();
}

// ---------------- persistent LSTM kernel ----------------
// L1 policy: W1/Wl slices (80KB) via .ca stay L1-resident (L1D = 228-106 = ~122KB);
// W2 (144KB, doesn't fit) and all z stream via .cg.
__global__ void __launch_bounds__(NTHR, 1) lstm_main(float* __restrict__ out) {
    extern __shared__ __align__(16) __half smem_dyn[];
    float (*s_g)[66] = reinterpret_cast<float(*)[66]>(smem_dyn);  // alias (fenced)

    uint32_t sA_s[STG], sB_s[STG];
    const uint32_t sbase = (uint32_t)__cvta_generic_to_shared(smem_dyn);
#pragma unroll
    for (int s = 0; s < STG; ++s) {
        sA_s[s] = sbase + (uint32_t)(s * STRIDE_ST) * 2;
        sB_s[s] = sA_s[s] + A_ST * 2;
    }
    const int tile = blockIdx.x;
    const int tid = threadIdx.x;
    unsigned ph = 0;

    for (int t = 0; t <= Tt; ++t) {
        const int p = t & 1;
        // ---- Phase A: gates1(t) on tiles 0..127 ; y(t-1) on tiles 128..135
        if (t < Tt) {
            if (tile < 128) {
                const int m0 = tile * 32;
                float acc[4] = {0.f, 0.f, 0.f, 0.f};
                Seg segs[3] = { { g_xh + (size_t)t * (Ii * Bb), Ii / CH },
                                { g_h1 + (size_t)(1 - p) * HB, Hh / CH },
                                { nullptr, 0 } };
                gemm_tile(g_W1 + (size_t)m0 * K1, K1, 1, segs, K1 / CH, acc,
                          tid, sA_s, sB_s);
                epi_gates(acc, tid, m0, g_b1, g_c1, g_h1 + (size_t)p * HB, s_g);
            } else if (t > 0) {
                do_y(tile, t - 1, p, out, tid, sA_s, sB_s);
            }
        } else {
            if (tile >= 128) do_y(tile, t - 1, p, out, tid, sA_s, sB_s);
            break;
        }
        ph++; gbar(ph * NBLK);
        // ---- Phase B: gates2(t) on tiles 0..127
        if (tile < 128) {
            const int m0 = tile * 32;
            float acc[4] = {0.f, 0.f, 0.f, 0.f};
            Seg segs[3] = { { g_xh + (size_t)t * (Ii * Bb), Ii / CH },
                            { g_h1 + (size_t)p * HB, Hh / CH },
                            { g_h2 + (size_t)p * HB, Hh / CH } };
            gemm_tile(g_W2 + (size_t)m0 * K2, K2, 0, segs, K2 / CH, acc,
                      tid, sA_s, sB_s);
            epi_gates(acc, tid, m0, g_b2, g_c2, g_h2 + (size_t)(1 - p) * HB, s_g);
        }
        ph++; gbar(ph * NBLK);
    }
}

// ---------------- launch ----------------
extern "C" void kernel_launch(void* const* d_in, const int* in_sizes, int n_in,
                              void* d_out, int out_size) {
    const float* x    = (const float*)d_in[0];
    const float* Wih1 = (const float*)d_in[1];
    const float* Whh1 = (const float*)d_in[2];
    const float* bih1 = (const float*)d_in[3];
    const float* bhh1 = (const float*)d_in[4];
    const float* Wih2 = (const float*)d_in[5];
    const float* Whh2 = (const float*)d_in[6];
    const float* bih2 = (const float*)d_in[7];
    const float* bhh2 = (const float*)d_in[8];
    const float* Wl   = (const float*)d_in[9];
    const float* bl   = (const float*)d_in[10];
    float* out = (float*)d_out;

    cudaFuncSetAttribute(lstm_main, cudaFuncAttributeMaxDynamicSharedMemorySize,
                         SMEM_BYTES);

    const size_t nprep = (size_t)Gg * K2;
    prep_all<<<(unsigned)((nprep + 255) / 256), 256>>>(
        x, Wih1, Whh1, bih1, bhh1, Wih2, Whh2, bih2, bhh2, Wl, bl);
    lstm_main<<<NBLK, NTHR, SMEM_BYTES>>>(out);
}

// round 8
// speedup vs baseline: 2.0562x; 1.2325x over previous
#include <cuda_runtime.h>
#include <cuda_fp16.h>
#include <cstdint>

#define Bb   64
#define Tt   256
#define Ii   256
#define Hh   1024
#define Gg   4096
#define Oo   256
#define NBLK 136
#define NTHR 512
#define CH   128           // k per chunk
#define APAD 136           // A smem row stride (halves): conflict-free ldmatrix
#define BPAD 72            // B smem row stride (halves): conflict-free ldmatrix
#define ACH  (32 * APAD)   // 4352 halves per A chunk (8704 B)
#define BCH  (CH * BPAD)   // 9216 halves per B chunk (18432 B)
#define ABYTES (ACH * 2)
#define BBYTES (BCH * 2)
#define STG  4
#define STRIDE_ST (ACH + BCH)                  // 13568 halves / stage
#define SMEM_BYTES (STG * STRIDE_ST * 2 + 64)  // stages + mbarriers

#define W1CH 10            // chunks: (I+H)/128
#define W2CH 18            // (I+H+H)/128
#define XCH  2             // I/128
#define HCH  8             // H/128
#define HPH  (HCH * BCH)   // halves per h parity buffer (73728)

// ---------------- device-global scratch (packed smem images) ----------------
__device__ __align__(16) __half g_W1p[(size_t)128 * W1CH * ACH];
__device__ __align__(16) __half g_W2p[(size_t)128 * W2CH * ACH];
__device__ __align__(16) __half g_Wlp[(size_t)8 * W1CH * ACH];
__device__ __align__(16) __half g_xp [(size_t)Tt * XCH * BCH];   // [t][chunk][k][72]
__device__ __align__(16) __half g_h1p[2 * HPH];                  // [parity][u][72]
__device__ __align__(16) __half g_h2p[2 * HPH];
__device__ float g_c1[Hh * Bb];
__device__ float g_c2[Hh * Bb];
__device__ float g_b1[Gg];
__device__ float g_b2[Gg];
__device__ float g_bl[Oo];
__device__ unsigned g_bar;

// ---------------- merged prep kernel: pack everything ----------------
__global__ void prep_all(
    const float* __restrict__ x,
    const float* __restrict__ Wih1, const float* __restrict__ Whh1,
    const float* __restrict__ bi1,  const float* __restrict__ bh1,
    const float* __restrict__ Wih2, const float* __restrict__ Whh2,
    const float* __restrict__ bi2,  const float* __restrict__ bh2,
    const float* __restrict__ Wl,   const float* __restrict__ bl)
{
    const size_t idx = (size_t)blockIdx.x * blockDim.x + threadIdx.x;

    // W2p: [tile 128][chunk 18][row 32][col 136]
    if (idx < (size_t)128 * W2CH * ACH) {
        int tile = (int)(idx / (W2CH * ACH));
        int r1 = (int)(idx - (size_t)tile * (W2CH * ACH));
        int chunk = r1 / ACH, r2 = r1 - chunk * ACH;
        int row = r2 / APAD, col = r2 - row * APAD;
        float v = 0.f;
        if (col < CH) {
            int gr = tile * 32 + row;
            int u = gr >> 2, gt = gr & 3, orow = gt * Hh + u;
            int k = chunk * CH + col;
            v = (k < Ii + Hh) ? Wih2[(size_t)orow * (Ii + Hh) + k]
                              : Whh2[(size_t)orow * Hh + (k - (Ii + Hh))];
        }
        g_W2p[idx] = __float2half(v);
    }
    // W1p: [tile 128][chunk 10][row 32][col 136]
    if (idx < (size_t)128 * W1CH * ACH) {
        int tile = (int)(idx / (W1CH * ACH));
        int r1 = (int)(idx - (size_t)tile * (W1CH * ACH));
        int chunk = r1 / ACH, r2 = r1 - chunk * ACH;
        int row = r2 / APAD, col = r2 - row * APAD;
        float v = 0.f;
        if (col < CH) {
            int gr = tile * 32 + row;
            int u = gr >> 2, gt = gr & 3, orow = gt * Hh + u;
            int k = chunk * CH + col;
            v = (k < Ii) ? Wih1[(size_t)orow * Ii + k]
                         : Whh1[(size_t)orow * Hh + (k - Ii)];
        }
        g_W1p[idx] = __float2half(v);
    }
    // Wlp: [tile 8][chunk 10][row 32][col 136] (no gate permute)
    if (idx < (size_t)8 * W1CH * ACH) {
        int tile = (int)(idx / (W1CH * ACH));
        int r1 = (int)(idx - (size_t)tile * (W1CH * ACH));
        int chunk = r1 / ACH, r2 = r1 - chunk * ACH;
        int row = r2 / APAD, col = r2 - row * APAD;
        float v = 0.f;
        if (col < CH) {
            int m = tile * 32 + row;
            int k = chunk * CH + col;
            v = Wl[(size_t)m * (Ii + Hh) + k];
        }
        g_Wlp[idx] = __float2half(v);
    }
    // xp: [t][chunk 2][krow 128][col 72]
    if (idx < (size_t)Tt * XCH * BCH) {
        int t = (int)(idx / (XCH * BCH));
        int r1 = (int)(idx - (size_t)t * (XCH * BCH));
        int chunk = r1 / BCH, r2 = r1 - chunk * BCH;
        int krow = r2 / BPAD, col = r2 - krow * BPAD;
        float v = 0.f;
        if (col < Bb) {
            int i = chunk * CH + krow;
            v = x[((size_t)col * Tt + t) * Ii + i];
        }
        g_xp[idx] = __float2half(v);
    }
    if (idx < 2 * HPH) { g_h1p[idx] = __float2half(0.f); g_h2p[idx] = __float2half(0.f); }
    if (idx < Hh * Bb) { g_c1[idx] = 0.f; g_c2[idx] = 0.f; }
    if (idx < Gg) {
        int u = (int)idx >> 2, gt = (int)idx & 3;
        g_b1[idx] = bi1[gt * Hh + u] + bh1[gt * Hh + u];
        g_b2[idx] = bi2[gt * Hh + u] + bh2[gt * Hh + u];
    }
    if (idx < Oo) g_bl[idx] = bl[idx];
    if (idx == 0) g_bar = 0u;
}

// ---------------- helpers ----------------
struct Seg { const __half* z; int chunks; };

__device__ __forceinline__ float sigf(float x) { return 1.f / (1.f + __expf(-x)); }

// fence-free grid barrier: h is produced via st.global (L2) and consumed via
// TMA bulk loads (read through L2, bypass L1) -> release/acquire suffices.
__device__ __forceinline__ void gbar(unsigned target) {
    __syncthreads();
    if (threadIdx.x == 0) {
        asm volatile("red.release.gpu.global.add.u32 [%0], %1;\n"
                     :: "l"(&g_bar), "r"(1u) : "memory");
        unsigned v;
        do {
            asm volatile("ld.acquire.gpu.global.u32 %0, [%1];\n"
                         : "=r"(v) : "l"(&g_bar) : "memory");
        } while (v < target);
    }
    __syncthreads();
}

__device__ __forceinline__ void mbar_wait(uint32_t bar, unsigned parity) {
    asm volatile(
        "{\n\t.reg .pred P;\n"
        "WAIT_%=:\n\t"
        "mbarrier.try_wait.parity.shared.b64 P, [%0], %1;\n\t"
        "@P bra.uni DONE_%=;\n\t"
        "bra.uni WAIT_%=;\n"
        "DONE_%=:\n\t}"
        :: "r"(bar), "r"(parity) : "memory");
}

// issue one chunk's two bulk copies (tid 0 only)
__device__ __forceinline__ void issue_chunk(
    const __half* __restrict__ Wp, int j, const Seg segs[3],
    uint32_t sA, uint32_t sB, uint32_t bar)
{
    asm volatile("mbarrier.arrive.expect_tx.shared.b64 _, [%0], %1;\n"
                 :: "r"(bar), "r"(ABYTES + BBYTES) : "memory");
    asm volatile("cp.async.bulk.shared::cta.global.mbarrier::complete_tx::bytes "
                 "[%0], [%1], %2, [%3];\n"
                 :: "r"(sA), "l"(Wp + (size_t)j * ACH), "r"(ABYTES), "r"(bar)
                 : "memory");
    int jj = j, s = 0;
    if (jj >= segs[0].chunks) { jj -= segs[0].chunks; s = 1; }
    if (s == 1 && jj >= segs[1].chunks) { jj -= segs[1].chunks; s = 2; }
    const __half* z = segs[s].z + (size_t)jj * BCH;
    asm volatile("cp.async.bulk.shared::cta.global.mbarrier::complete_tx::bytes "
                 "[%0], [%1], %2, [%3];\n"
                 :: "r"(sB), "l"(z), "r"(BBYTES), "r"(bar)
                 : "memory");
}

// compute one 128-k chunk: warp tile 16m x 8n; 8 x (ldmatrix.x4 + x2.trans + mma)
__device__ __forceinline__ void compute_chunk(
    uint32_t sAaddr, uint32_t sBaddr, float acc[4], int lane, int wm, int wn)
{
    const int r16 = lane & 15, cs = lane >> 4;
    const int bl8 = lane & 7, bm = (lane >> 3) & 1;
#pragma unroll
    for (int k16 = 0; k16 < 8; ++k16) {
        const int kb = k16 * 16;
        uint32_t aaddr = sAaddr + (uint32_t)((wm * 16 + r16) * APAD + kb + cs * 8) * 2;
        uint32_t baddr = sBaddr + (uint32_t)((kb + bl8 + 8 * bm) * BPAD + wn * 8) * 2;
        unsigned a0, a1, a2, a3, b0, b1;
        asm volatile("ldmatrix.sync.aligned.m8n8.x4.shared.b16 {%0,%1,%2,%3}, [%4];\n"
                     : "=r"(a0), "=r"(a1), "=r"(a2), "=r"(a3) : "r"(aaddr));
        asm volatile("ldmatrix.sync.aligned.m8n8.x2.trans.shared.b16 {%0,%1}, [%2];\n"
                     : "=r"(b0), "=r"(b1) : "r"(baddr));
        asm volatile("mma.sync.aligned.m16n8k16.row.col.f32.f16.f16.f32 "
                     "{%0,%1,%2,%3}, {%4,%5,%6,%7}, {%8,%9}, {%0,%1,%2,%3};\n"
                     : "+f"(acc[0]), "+f"(acc[1]), "+f"(acc[2]), "+f"(acc[3])
                     : "r"(a0), "r"(a1), "r"(a2), "r"(a3), "r"(b0), "r"(b1));
    }
}

// TMA-bulk pipelined 32x64 GEMM over nch 128-k chunks
__device__ __forceinline__ void gemm_tile(
    const __half* __restrict__ Wp, const Seg segs[3], int nch,
    float acc[4], int tid, const uint32_t sA_s[STG], const uint32_t sB_s[STG],
    uint32_t bar0, unsigned& phases)
{
    const int lane = tid & 31, wid = tid >> 5;
    const int wm = wid & 1, wn = wid >> 1;
    if (tid == 0) {
        asm volatile("fence.proxy.async.shared::cta;\n" ::: "memory");
#pragma unroll
        for (int j0 = 0; j0 < STG - 1; ++j0)
            if (j0 < nch)
                issue_chunk(Wp, j0, segs, sA_s[j0], sB_s[j0], bar0 + j0 * 8);
    }
    int st = 0, stn = STG - 1;
    for (int j = 0; j < nch; ++j) {
        mbar_wait(bar0 + st * 8, (phases >> st) & 1u);
        phases ^= (1u << st);
        __syncthreads();              // all warps past chunk j-1's compute
        const int jn = j + (STG - 1);
        if (tid == 0 && jn < nch)
            issue_chunk(Wp, jn, segs, sA_s[stn], sB_s[stn], bar0 + stn * 8);
        compute_chunk(sA_s[st], sB_s[st], acc, lane, wm, wn);
        st  = (st  == STG - 1) ? 0 : st  + 1;
        stn = (stn == STG - 1) ? 0 : stn + 1;
    }
}

// LSTM pointwise: rows are 4u+gate -> CTA owns 8 full units; h written in
// padded B-image layout [u][72] for the consumers' bulk loads.
__device__ __forceinline__ void epi_gates(
    float acc[4], int tid, int m0, const float* __restrict__ bias,
    float* __restrict__ cbuf, __half* __restrict__ hdst, float (*s_g)[66])
{
    const int wid = tid >> 5, lane = tid & 31;
    const int grp = lane >> 2, tig = lane & 3;
    const int wm = wid & 1, wn = wid >> 1;
    const int m = wm * 16 + grp;
    const int n = wn * 8 + tig * 2;
    __syncthreads();   // s_g aliases stage smem; all gemm smem reads done
    s_g[m][n] = acc[0];      s_g[m][n + 1] = acc[1];
    s_g[m + 8][n] = acc[2];  s_g[m + 8][n + 1] = acc[3];
    __syncthreads();
    const int u0 = m0 >> 2;
    {
        const int du = tid >> 6, b = tid & 63;   // 512 threads = 8 units x 64 b
        float ig = s_g[4 * du + 0][b] + bias[m0 + 4 * du + 0];
        float fg = s_g[4 * du + 1][b] + bias[m0 + 4 * du + 1];
        float gg = s_g[4 * du + 2][b] + bias[m0 + 4 * du + 2];
        float og = s_g[4 * du + 3][b] + bias[m0 + 4 * du + 3];
        const int u = u0 + du;
        const int ci = u * Bb + b;
        float c = cbuf[ci];
        float cn = sigf(fg) * c + sigf(ig) * tanhf(gg);
        cbuf[ci] = cn;
        hdst[(size_t)u * BPAD + b] = __float2half(sigf(og) * tanhf(cn));
    }
    __syncthreads();   // STS drained by BAR before next gemm's bulk writes
}

__device__ __forceinline__ void do_y(
    int tile, int t_y, int p, float* __restrict__ out, int tid,
    const uint32_t sA_s[STG], const uint32_t sB_s[STG], uint32_t bar0,
    unsigned& phases)
{
    const int m0 = (tile - 128) * 32;
    float acc[4] = {0.f, 0.f, 0.f, 0.f};
    Seg segs[3] = { { g_xp + (size_t)t_y * (XCH * BCH), XCH },
                    { g_h2p + (size_t)p * HPH, HCH },
                    { nullptr, 0 } };
    gemm_tile(g_Wlp + (size_t)(tile - 128) * (W1CH * ACH), segs, W1CH + HCH? (XCH + HCH) : 0,
              acc, tid, sA_s, sB_s, bar0, phases);
    const int wid = tid >> 5, lane = tid & 31;
    const int grp = lane >> 2, tig = lane & 3;
    const int wm = wid & 1, wn = wid >> 1;
    const int m = m0 + wm * 16 + grp;
    const int n = wn * 8 + tig * 2;   // batch
    const size_t r0 = (size_t)n * (Tt * Oo) + (size_t)t_y * Oo;
    const size_t r1 = (size_t)(n + 1) * (Tt * Oo) + (size_t)t_y * Oo;
    out[r0 + m]     = acc[0] + g_bl[m];
    out[r1 + m]     = acc[1] + g_bl[m];
    out[r0 + m + 8] = acc[2] + g_bl[m + 8];
    out[r1 + m + 8] = acc[3] + g_bl[m + 8];
    __syncthreads();
}

// ---------------- persistent LSTM kernel ----------------
__global__ void __launch_bounds__(NTHR, 1) lstm_main(float* __restrict__ out) {
    extern __shared__ __align__(16) __half smem_dyn[];
    float (*s_g)[66] = reinterpret_cast<float(*)[66]>(smem_dyn);  // alias (fenced)

    uint32_t sA_s[STG], sB_s[STG];
    const uint32_t sbase = (uint32_t)__cvta_generic_to_shared(smem_dyn);
#pragma unroll
    for (int s = 0; s < STG; ++s) {
        sA_s[s] = sbase + (uint32_t)(s * STRIDE_ST) * 2;
        sB_s[s] = sA_s[s] + ACH * 2;
    }
    const uint32_t bar0 = sbase + (uint32_t)(STG * STRIDE_ST) * 2;
    if (threadIdx.x == 0) {
#pragma unroll
        for (int s = 0; s < STG; ++s)
            asm volatile("mbarrier.init.shared.b64 [%0], 1;\n"
                         :: "r"(bar0 + s * 8) : "memory");
        asm volatile("fence.proxy.async.shared::cta;\n" ::: "memory");
    }
    __syncthreads();

    const int tile = blockIdx.x;
    const int tid = threadIdx.x;
    unsigned ph = 0;
    unsigned phases = 0;

    for (int t = 0; t <= Tt; ++t) {
        const int p = t & 1;
        // ---- Phase A: gates1(t) on tiles 0..127 ; y(t-1) on tiles 128..135
        if (t < Tt) {
            if (tile < 128) {
                const int m0 = tile * 32;
                float acc[4] = {0.f, 0.f, 0.f, 0.f};
                Seg segs[3] = { { g_xp + (size_t)t * (XCH * BCH), XCH },
                                { g_h1p + (size_t)(1 - p) * HPH, HCH },
                                { nullptr, 0 } };
                gemm_tile(g_W1p + (size_t)tile * (W1CH * ACH), segs, XCH + HCH,
                          acc, tid, sA_s, sB_s, bar0, phases);
                epi_gates(acc, tid, m0, g_b1, g_c1, g_h1p + (size_t)p * HPH, s_g);
            } else if (t > 0) {
                do_y(tile, t - 1, p, out, tid, sA_s, sB_s, bar0, phases);
            }
        } else {
            if (tile >= 128) do_y(tile, t - 1, p, out, tid, sA_s, sB_s, bar0, phases);
            break;
        }
        ph++; gbar(ph * NBLK);
        // ---- Phase B: gates2(t) on tiles 0..127
        if (tile < 128) {
            const int m0 = tile * 32;
            float acc[4] = {0.f, 0.f, 0.f, 0.f};
            Seg segs[3] = { { g_xp + (size_t)t * (XCH * BCH), XCH },
                            { g_h1p + (size_t)p * HPH, HCH },
                            { g_h2p + (size_t)p * HPH, HCH } };
            gemm_tile(g_W2p + (size_t)tile * (W2CH * ACH), segs, XCH + 2 * HCH,
                      acc, tid, sA_s, sB_s, bar0, phases);
            epi_gates(acc, tid, m0, g_b2, g_c2, g_h2p + (size_t)(1 - p) * HPH, s_g);
        }
        ph++; gbar(ph * NBLK);
    }
}

// ---------------- launch ----------------
extern "C" void kernel_launch(void* const* d_in, const int* in_sizes, int n_in,
                              void* d_out, int out_size) {
    const float* x    = (const float*)d_in[0];
    const float* Wih1 = (const float*)d_in[1];
    const float* Whh1 = (const float*)d_in[2];
    const float* bih1 = (const float*)d_in[3];
    const float* bhh1 = (const float*)d_in[4];
    const float* Wih2 = (const float*)d_in[5];
    const float* Whh2 = (const float*)d_in[6];
    const float* bih2 = (const float*)d_in[7];
    const float* bhh2 = (const float*)d_in[8];
    const float* Wl   = (const float*)d_in[9];
    const float* bl   = (const float*)d_in[10];
    float* out = (float*)d_out;

    cudaFuncSetAttribute(lstm_main, cudaFuncAttributeMaxDynamicSharedMemorySize,
                         SMEM_BYTES);

    const size_t nprep = (size_t)128 * W2CH * ACH;   // largest packed array
    prep_all<<<(unsigned)((nprep + 255) / 256), 256>>>(
        x, Wih1, Whh1, bih1, bhh1, Wih2, Whh2, bih2, bhh2, Wl, bl);
    lstm_main<<<NBLK, NTHR, SMEM_BYTES>>>(out);
}

// round 10
// speedup vs baseline: 2.6916x; 1.3090x over previous
#include <cuda_runtime.h>
#include <cuda_fp16.h>
#include <cstdint>

#define Bb   64
#define Tt   256
#define Ii   256
#define Hh   1024
#define Gg   4096
#define Oo   256
#define NBLK 136
#define NTHR 512
#define CH   128           // k per chunk
#define APAD 136           // A smem row stride (halves): conflict-free ldmatrix
#define BPAD 72            // B smem row stride (halves): conflict-free ldmatrix
#define ACH  (32 * APAD)   // 4352 halves per A chunk (8704 B)
#define BCH  (CH * BPAD)   // 9216 halves per B chunk (18432 B)
#define ABYTES (ACH * 2)
#define BBYTES (BCH * 2)
#define STG  4
#define STRIDE_ST (ACH + BCH)                  // 13568 halves / stage
#define SMEM_BYTES (STG * STRIDE_ST * 2 + 64)  // stages + mbarriers

#define W1CH 10            // chunks: (I+H)/128
#define W2CH 18            // (I+H+H)/128
#define XCH  2             // I/128
#define HCH  8             // H/128
#define HPH  (HCH * BCH)   // halves per h parity buffer
#define RSLAB 1056         // 32*33 floats per k-group partial slab

// ---------------- device-global scratch (packed smem images) ----------------
__device__ __align__(16) __half g_W1p[(size_t)128 * W1CH * ACH];
__device__ __align__(16) __half g_W2p[(size_t)128 * W2CH * ACH];
__device__ __align__(16) __half g_Wlp[(size_t)8 * W1CH * ACH];
__device__ __align__(16) __half g_xp [(size_t)Tt * XCH * BCH];   // [t][chunk][k][72]
__device__ __align__(16) __half g_h1p[2 * HPH];                  // [parity][u][72]
__device__ __align__(16) __half g_h2p[2 * HPH];
__device__ float g_c1[Hh * Bb];
__device__ float g_c2[Hh * Bb];
__device__ float g_b1[Gg];
__device__ float g_b2[Gg];
__device__ float g_bl[Oo];
__device__ unsigned g_bar;

// ---------------- merged prep kernel: pack everything ----------------
__global__ void prep_all(
    const float* __restrict__ x,
    const float* __restrict__ Wih1, const float* __restrict__ Whh1,
    const float* __restrict__ bi1,  const float* __restrict__ bh1,
    const float* __restrict__ Wih2, const float* __restrict__ Whh2,
    const float* __restrict__ bi2,  const float* __restrict__ bh2,
    const float* __restrict__ Wl,   const float* __restrict__ bl)
{
    const size_t idx = (size_t)blockIdx.x * blockDim.x + threadIdx.x;

    // W2p: [tile 128][chunk 18][row 32][col 136]
    if (idx < (size_t)128 * W2CH * ACH) {
        int tile = (int)(idx / (W2CH * ACH));
        int r1 = (int)(idx - (size_t)tile * (W2CH * ACH));
        int chunk = r1 / ACH, r2 = r1 - chunk * ACH;
        int row = r2 / APAD, col = r2 - row * APAD;
        float v = 0.f;
        if (col < CH) {
            int gr = tile * 32 + row;
            int u = gr >> 2, gt = gr & 3, orow = gt * Hh + u;
            int k = chunk * CH + col;
            v = (k < Ii + Hh) ? Wih2[(size_t)orow * (Ii + Hh) + k]
                              : Whh2[(size_t)orow * Hh + (k - (Ii + Hh))];
        }
        g_W2p[idx] = __float2half(v);
    }
    // W1p: [tile 128][chunk 10][row 32][col 136]
    if (idx < (size_t)128 * W1CH * ACH) {
        int tile = (int)(idx / (W1CH * ACH));
        int r1 = (int)(idx - (size_t)tile * (W1CH * ACH));
        int chunk = r1 / ACH, r2 = r1 - chunk * ACH;
        int row = r2 / APAD, col = r2 - row * APAD;
        float v = 0.f;
        if (col < CH) {
            int gr = tile * 32 + row;
            int u = gr >> 2, gt = gr & 3, orow = gt * Hh + u;
            int k = chunk * CH + col;
            v = (k < Ii) ? Wih1[(size_t)orow * Ii + k]
                         : Whh1[(size_t)orow * Hh + (k - Ii)];
        }
        g_W1p[idx] = __float2half(v);
    }
    // Wlp: [tile 8][chunk 10][row 32][col 136] (no gate permute)
    if (idx < (size_t)8 * W1CH * ACH) {
        int tile = (int)(idx / (W1CH * ACH));
        int r1 = (int)(idx - (size_t)tile * (W1CH * ACH));
        int chunk = r1 / ACH, r2 = r1 - chunk * ACH;
        int row = r2 / APAD, col = r2 - row * APAD;
        float v = 0.f;
        if (col < CH) {
            int m = tile * 32 + row;
            int k = chunk * CH + col;
            v = Wl[(size_t)m * (Ii + Hh) + k];
        }
        g_Wlp[idx] = __float2half(v);
    }
    // xp: [t][chunk 2][krow 128][col 72]
    if (idx < (size_t)Tt * XCH * BCH) {
        int t = (int)(idx / (XCH * BCH));
        int r1 = (int)(idx - (size_t)t * (XCH * BCH));
        int chunk = r1 / BCH, r2 = r1 - chunk * BCH;
        int krow = r2 / BPAD, col = r2 - krow * BPAD;
        float v = 0.f;
        if (col < Bb) {
            int i = chunk * CH + krow;
            v = x[((size_t)col * Tt + t) * Ii + i];
        }
        g_xp[idx] = __float2half(v);
    }
    if (idx < 2 * HPH) { g_h1p[idx] = __float2half(0.f); g_h2p[idx] = __float2half(0.f); }
    if (idx < Hh * Bb) { g_c1[idx] = 0.f; g_c2[idx] = 0.f; }
    if (idx < Gg) {
        int u = (int)idx >> 2, gt = (int)idx & 3;
        g_b1[idx] = bi1[gt * Hh + u] + bh1[gt * Hh + u];
        g_b2[idx] = bi2[gt * Hh + u] + bh2[gt * Hh + u];
    }
    if (idx < Oo) g_bl[idx] = bl[idx];
    if (idx == 0) g_bar = 0u;
}

// ---------------- helpers ----------------
struct Seg { const __half* z; int chunks; };

__device__ __forceinline__ float sigf(float x) { return 1.f / (1.f + __expf(-x)); }

// fence-free grid barrier: h is produced via st.global (L2) and consumed via
// TMA bulk loads (read through L2, bypass L1) -> release/acquire suffices.
__device__ __forceinline__ void gbar(unsigned target) {
    __syncthreads();
    if (threadIdx.x == 0) {
        asm volatile("red.release.gpu.global.add.u32 [%0], %1;\n"
                     :: "l"(&g_bar), "r"(1u) : "memory");
        unsigned v;
        do {
            asm volatile("ld.acquire.gpu.global.u32 %0, [%1];\n"
                         : "=r"(v) : "l"(&g_bar) : "memory");
        } while (v < target);
    }
    __syncthreads();
}

__device__ __forceinline__ void mbar_wait(uint32_t bar, unsigned parity) {
    asm volatile(
        "{\n\t.reg .pred P;\n"
        "WAIT_%=:\n\t"
        "mbarrier.try_wait.parity.shared.b64 P, [%0], %1;\n\t"
        "@P bra.uni DONE_%=;\n\t"
        "bra.uni WAIT_%=;\n"
        "DONE_%=:\n\t}"
        :: "r"(bar), "r"(parity) : "memory");
}

// issue one chunk's two bulk copies (tid 0 only)
__device__ __forceinline__ void issue_chunk(
    const __half* __restrict__ Wp, int j, const Seg segs[3],
    uint32_t sA, uint32_t sB, uint32_t bar)
{
    asm volatile("mbarrier.arrive.expect_tx.shared.b64 _, [%0], %1;\n"
                 :: "r"(bar), "r"(ABYTES + BBYTES) : "memory");
    asm volatile("cp.async.bulk.shared::cta.global.mbarrier::complete_tx::bytes "
                 "[%0], [%1], %2, [%3];\n"
                 :: "r"(sA), "l"(Wp + (size_t)j * ACH), "r"(ABYTES), "r"(bar)
                 : "memory");
    int jj = j, s = 0;
    if (jj >= segs[0].chunks) { jj -= segs[0].chunks; s = 1; }
    if (s == 1 && jj >= segs[1].chunks) { jj -= segs[1].chunks; s = 2; }
    const __half* z = segs[s].z + (size_t)jj * BCH;
    asm volatile("cp.async.bulk.shared::cta.global.mbarrier::complete_tx::bytes "
                 "[%0], [%1], %2, [%3];\n"
                 :: "r"(sB), "l"(z), "r"(BBYTES), "r"(bar)
                 : "memory");
}

// compute one 128-k chunk; warp owns 32m x 32n x 16k:
// g = k-group (wid & 7), nh = n-half (wid >> 3)
// 2x ldmatrix.x4 (A) + 2x ldmatrix.x4.trans (B) + 8x mma.m16n8k16
__device__ __forceinline__ void compute_chunk(
    uint32_t sAaddr, uint32_t sBaddr, float (&acc)[8][4], int lane, int g, int nh)
{
    const int r16 = lane & 15, cs = lane >> 4;
    const int kb = g * 16;
    unsigned a[2][4], b[2][4];
#pragma unroll
    for (int mi = 0; mi < 2; ++mi) {
        uint32_t aaddr = sAaddr +
            (uint32_t)((mi * 16 + r16) * APAD + kb + cs * 8) * 2;
        asm volatile("ldmatrix.sync.aligned.m8n8.x4.shared.b16 {%0,%1,%2,%3}, [%4];\n"
                     : "=r"(a[mi][0]), "=r"(a[mi][1]), "=r"(a[mi][2]), "=r"(a[mi][3])
                     : "r"(aaddr));
    }
#pragma unroll
    for (int nq = 0; nq < 2; ++nq) {
        uint32_t baddr = sBaddr +
            (uint32_t)((kb + r16) * BPAD + nh * 32 + nq * 16 + cs * 8) * 2;
        asm volatile("ldmatrix.sync.aligned.m8n8.x4.trans.shared.b16 {%0,%1,%2,%3}, [%4];\n"
                     : "=r"(b[nq][0]), "=r"(b[nq][1]), "=r"(b[nq][2]), "=r"(b[nq][3])
                     : "r"(baddr));
    }
#pragma unroll
    for (int mi = 0; mi < 2; ++mi)
#pragma unroll
        for (int nj = 0; nj < 4; ++nj) {
            float* c = acc[mi * 4 + nj];
            asm volatile("mma.sync.aligned.m16n8k16.row.col.f32.f16.f16.f32 "
                         "{%0,%1,%2,%3}, {%4,%5,%6,%7}, {%8,%9}, {%0,%1,%2,%3};\n"
                         : "+f"(c[0]), "+f"(c[1]), "+f"(c[2]), "+f"(c[3])
                         : "r"(a[mi][0]), "r"(a[mi][1]), "r"(a[mi][2]), "r"(a[mi][3]),
                           "r"(b[nj >> 1][(nj & 1) * 2]),
                           "r"(b[nj >> 1][(nj & 1) * 2 + 1]));
        }
}

// TMA-bulk pipelined 32x64 GEMM over nch 128-k chunks (k split across warps)
__device__ __forceinline__ void gemm_tile(
    const __half* __restrict__ Wp, const Seg segs[3], int nch,
    float (&acc)[8][4], int tid, const uint32_t sA_s[STG], const uint32_t sB_s[STG],
    uint32_t bar0, unsigned& phases)
{
    const int lane = tid & 31, wid = tid >> 5;
    const int g = wid & 7, nh = wid >> 3;
    if (tid == 0) {
        asm volatile("fence.proxy.async.shared::cta;\n" ::: "memory");
#pragma unroll
        for (int j0 = 0; j0 < STG - 1; ++j0)
            if (j0 < nch)
                issue_chunk(Wp, j0, segs, sA_s[j0], sB_s[j0], bar0 + j0 * 8);
    }
    int st = 0, stn = STG - 1;
    for (int j = 0; j < nch; ++j) {
        mbar_wait(bar0 + st * 8, (phases >> st) & 1u);
        phases ^= (1u << st);
        __syncthreads();              // all warps past chunk j-1's compute
        const int jn = j + (STG - 1);
        if (tid == 0 && jn < nch)
            issue_chunk(Wp, jn, segs, sA_s[stn], sB_s[stn], bar0 + stn * 8);
        compute_chunk(sA_s[st], sB_s[st], acc, lane, g, nh);
        st  = (st  == STG - 1) ? 0 : st  + 1;
        stn = (stn == STG - 1) ? 0 : stn + 1;
    }
}

// write each warp's k-group partial acc to its smem slab [32][33] f32
__device__ __forceinline__ void reduce_store(float (&acc)[8][4], int tid, char* smal)
{
    const int wid = tid >> 5, lane = tid & 31;
    float* slab = (float*)smal + wid * RSLAB;
    const int r = lane >> 2, c2 = (lane & 3) * 2;
#pragma unroll
    for (int mi = 0; mi < 2; ++mi)
#pragma unroll
        for (int nj = 0; nj < 4; ++nj) {
            float* p = slab + (mi * 16 + r) * 33 + nj * 8 + c2;
            p[0] = acc[mi * 4 + nj][0];
            p[1] = acc[mi * 4 + nj][1];
            p[33 * 8]     = acc[mi * 4 + nj][2];
            p[33 * 8 + 1] = acc[mi * 4 + nj][3];
        }
}

// LSTM pointwise: rows are 4u+gate -> CTA owns 8 full units; h written in the
// packed B-image layout [u][72].
__device__ __forceinline__ void epi_gates(
    float (&acc)[8][4], int tid, int m0, const float* __restrict__ bias,
    float* __restrict__ cbuf, __half* __restrict__ hdst, char* smal)
{
    __syncthreads();                  // all warps done reading stages
    reduce_store(acc, tid, smal);     // partials alias stage smem
    __syncthreads();
    const float* red = (const float*)smal;
    const int du = tid >> 6, b = tid & 63;     // 8 units x 64 batch
    const int nh = b >> 5, nl = b & 31;
    float gs[4];
#pragma unroll
    for (int j = 0; j < 4; ++j) {
        float s = 0.f;
#pragma unroll
        for (int g = 0; g < 8; ++g)
            s += red[(nh * 8 + g) * RSLAB + (4 * du + j) * 33 + nl];
        gs[j] = s + bias[m0 + 4 * du + j];
    }
    const int u = (m0 >> 2) + du;
    const int ci = u * Bb + b;
    float c = cbuf[ci];
    float cn = sigf(gs[1]) * c + sigf(gs[0]) * tanhf(gs[2]);
    cbuf[ci] = cn;
    hdst[(size_t)u * BPAD + b] = __float2half(sigf(gs[3]) * tanhf(cn));
    __syncthreads();                  // generic writes done before next TMA issue
}

__device__ __forceinline__ void do_y(
    int tile, int t_y, int p, float* __restrict__ out, int tid,
    const uint32_t sA_s[STG], const uint32_t sB_s[STG], uint32_t bar0,
    unsigned& phases, char* smal)
{
    const int m0 = (tile - 128) * 32;
    float acc[8][4] = {};
    Seg segs[3] = { { g_xp + (size_t)t_y * (XCH * BCH), XCH },
                    { g_h2p + (size_t)p * HPH, HCH },
                    { nullptr, 0 } };
    gemm_tile(g_Wlp + (size_t)(tile - 128) * (W1CH * ACH), segs, XCH + HCH,
              acc, tid, sA_s, sB_s, bar0, phases);
    __syncthreads();
    reduce_store(acc, tid, smal);
    __syncthreads();
    const float* red = (const float*)smal;
    const int du = tid >> 6, b = tid & 63;
    const int nh = b >> 5, nl = b & 31;
    float4 v;
    float* vv = &v.x;
#pragma unroll
    for (int j = 0; j < 4; ++j) {
        float s = 0.f;
#pragma unroll
        for (int g = 0; g < 8; ++g)
            s += red[(nh * 8 + g) * RSLAB + (4 * du + j) * 33 + nl];
        vv[j] = s + g_bl[m0 + 4 * du + j];
    }
    *(float4*)(out + (size_t)b * (Tt * Oo) + (size_t)t_y * Oo + m0 + 4 * du) = v;
    __syncthreads();
}

// ---------------- persistent LSTM kernel ----------------
__global__ void __launch_bounds__(NTHR, 1) lstm_main(float* __restrict__ out) {
    extern __shared__ __align__(16) __half smem_dyn[];
    char* smal = (char*)smem_dyn;     // reduction slabs alias stage smem (fenced)

    uint32_t sA_s[STG], sB_s[STG];
    const uint32_t sbase = (uint32_t)__cvta_generic_to_shared(smem_dyn);
#pragma unroll
    for (int s = 0; s < STG; ++s) {
        sA_s[s] = sbase + (uint32_t)(s * STRIDE_ST) * 2;
        sB_s[s] = sA_s[s] + ACH * 2;
    }
    const uint32_t bar0 = sbase + (uint32_t)(STG * STRIDE_ST) * 2;
    if (threadIdx.x == 0) {
#pragma unroll
        for (int s = 0; s < STG; ++s)
            asm volatile("mbarrier.init.shared.b64 [%0], 1;\n"
                         :: "r"(bar0 + s * 8) : "memory");
        asm volatile("fence.proxy.async.shared::cta;\n" ::: "memory");
    }
    __syncthreads();

    const int tile = blockIdx.x;
    const int tid = threadIdx.x;
    unsigned ph = 0;
    unsigned phases = 0;

    for (int t = 0; t <= Tt; ++t) {
        const int p = t & 1;
        // ---- Phase A: gates1(t) on tiles 0..127 ; y(t-1) on tiles 128..135
        if (t < Tt) {
            if (tile < 128) {
                const int m0 = tile * 32;
                float acc[8][4] = {};
                Seg segs[3] = { { g_xp + (size_t)t * (XCH * BCH), XCH },
                                { g_h1p + (size_t)(1 - p) * HPH, HCH },
                                { nullptr, 0 } };
                gemm_tile(g_W1p + (size_t)tile * (W1CH * ACH), segs, XCH + HCH,
                          acc, tid, sA_s, sB_s, bar0, phases);
                epi_gates(acc, tid, m0, g_b1, g_c1, g_h1p + (size_t)p * HPH, smal);
            } else if (t > 0) {
                do_y(tile, t - 1, p, out, tid, sA_s, sB_s, bar0, phases, smal);
            }
        } else {
            if (tile >= 128)
                do_y(tile, t - 1, p, out, tid, sA_s, sB_s, bar0, phases, smal);
            break;
        }
        ph++; gbar(ph * NBLK);
        // ---- Phase B: gates2(t) on tiles 0..127
        if (tile < 128) {
            const int m0 = tile * 32;
            float acc[8][4] = {};
            Seg segs[3] = { { g_xp + (size_t)t * (XCH * BCH), XCH },
                            { g_h1p + (size_t)p * HPH, HCH },
                            { g_h2p + (size_t)p * HPH, HCH } };
            gemm_tile(g_W2p + (size_t)tile * (W2CH * ACH), segs, XCH + 2 * HCH,
                      acc, tid, sA_s, sB_s, bar0, phases);
            epi_gates(acc, tid, m0, g_b2, g_c2, g_h2p + (size_t)(1 - p) * HPH, smal);
        }
        ph++; gbar(ph * NBLK);
    }
}

// ---------------- launch ----------------
extern "C" void kernel_launch(void* const* d_in, const int* in_sizes, int n_in,
                              void* d_out, int out_size) {
    const float* x    = (const float*)d_in[0];
    const float* Wih1 = (const float*)d_in[1];
    const float* Whh1 = (const float*)d_in[2];
    const float* bih1 = (const float*)d_in[3];
    const float* bhh1 = (const float*)d_in[4];
    const float* Wih2 = (const float*)d_in[5];
    const float* Whh2 = (const float*)d_in[6];
    const float* bih2 = (const float*)d_in[7];
    const float* bhh2 = (const float*)d_in[8];
    const float* Wl   = (const float*)d_in[9];
    const float* bl   = (const float*)d_in[10];
    float* out = (float*)d_out;

    cudaFuncSetAttribute(lstm_main, cudaFuncAttributeMaxDynamicSharedMemorySize,
                         SMEM_BYTES);

    const size_t nprep = (size_t)128 * W2CH * ACH;   // largest packed array
    prep_all<<<(unsigned)((nprep + 255) / 256), 256>>>(
        x, Wih1, Whh1, bih1, bhh1, Wih2, Whh2, bih2, bhh2, Wl, bl);
    lstm_main<<<NBLK, NTHR, SMEM_BYTES>>>(out);
}